// round 5
// baseline (speedup 1.0000x reference)
#include <cuda_runtime.h>
#include <cuda_bf16.h>

// Problem constants (fixed by the dataset)
#define NMAX 50000
#define EMAX 800000
#define EEMAX (NMAX + EMAX)
#define DOUT 128
#define DIN 128
#define NEG_SLOPE 0.2f

// ---------------- scratch (device globals; no allocation allowed) ----------
__device__ float        g_xw[NMAX * DOUT];   // 25.6 MB
__device__ float        g_asrc[NMAX];
__device__ float        g_adst[NMAX];
__device__ unsigned int g_mkey[NMAX];        // ordered-int max keys
__device__ float        g_denom[NMAX];
__device__ float        g_e[EEMAX];          // e, then overwritten by exp(e-m)
__device__ int          g_is64;              // edge_index stored as int64?

// ---------------- float <-> monotone unsigned key (for atomicMax) ----------
__device__ __forceinline__ unsigned int fkey(float f) {
    unsigned int u = __float_as_uint(f);
    return u ^ ((u & 0x80000000u) ? 0xFFFFFFFFu : 0x80000000u);
}
__device__ __forceinline__ float keyf(unsigned int k) {
    unsigned int u = (k & 0x80000000u) ? (k ^ 0x80000000u) : ~k;
    return __uint_as_float(u);
}

// ---------------- edge-index decoding (int32 vs int64 buffers) -------------
// If the buffer is little-endian int64 with values < 2^31, every odd 32-bit
// word is 0. Random ids in [0,50000) make the detector exact in practice.
__global__ void k_detect(const int* __restrict__ w) {
    if (threadIdx.x == 0 && blockIdx.x == 0) {
        int odd_or = 0;
#pragma unroll
        for (int j = 0; j < 64; j++) odd_or |= w[2 * j + 1];
        g_is64 = (odd_or == 0) ? 1 : 0;
    }
}
__device__ __forceinline__ int edge_src(const int* w, int i, int is64) {
    return is64 ? w[2 * i] : w[i];
}
__device__ __forceinline__ int edge_dst(const int* w, int i, int E, int is64) {
    return is64 ? w[2 * (E + i)] : w[E + i];
}

// ---------------- 0) init: zero out accumulator + per-node state ----------
__global__ void k_init(float* __restrict__ out, int n) {
    int i = blockIdx.x * blockDim.x + threadIdx.x;
    int total = n * DOUT;
    if (i < total) out[i] = 0.0f;
    if (i < n) { g_mkey[i] = 0u; g_denom[i] = 0.0f; }
}

// ---------------- 1) GEMM: xw = x @ W  (BM=64, BK=16, per-thread 8x4) -----
__global__ __launch_bounds__(256, 3)
void k_gemm(const float* __restrict__ x, const float* __restrict__ W, int nrows) {
    __shared__ float As[16][64];    // [k][row]
    __shared__ float Bs[16][DOUT];  // [k][col]

    int tid = threadIdx.x;
    int row0 = blockIdx.x * 64;
    int ty = tid >> 5;   // 0..7  -> rows ty*8 .. ty*8+7
    int tx = tid & 31;   // 0..31 -> cols tx*4 .. tx*4+3

    float acc[8][4];
#pragma unroll
    for (int i = 0; i < 8; i++)
#pragma unroll
        for (int j = 0; j < 4; j++) acc[i][j] = 0.0f;

    int arow = tid >> 2;       // 0..63
    int kq = tid & 3;          // float4 index along K

    for (int k0 = 0; k0 < DIN; k0 += 16) {
        // stage A tile (64 x 16), transposed into [k][row]
        float4 av = make_float4(0.f, 0.f, 0.f, 0.f);
        int gr = row0 + arow;
        if (gr < nrows)
            av = *reinterpret_cast<const float4*>(x + (size_t)gr * DIN + k0 + 4 * kq);
        As[4 * kq + 0][arow] = av.x;
        As[4 * kq + 1][arow] = av.y;
        As[4 * kq + 2][arow] = av.z;
        As[4 * kq + 3][arow] = av.w;
        // stage B tile (16 x 128)
#pragma unroll
        for (int i = 0; i < 2; i++) {
            int fi = tid + i * 256;          // float4 index 0..511
            int bk = fi >> 5;                // 32 float4 per k-row
            int bc = (fi & 31) * 4;
            float4 bv = *reinterpret_cast<const float4*>(W + (size_t)(k0 + bk) * DOUT + bc);
            *reinterpret_cast<float4*>(&Bs[bk][bc]) = bv;
        }
        __syncthreads();

#pragma unroll
        for (int kk = 0; kk < 16; kk++) {
            float a[8];
#pragma unroll
            for (int i = 0; i < 8; i++) a[i] = As[kk][ty * 8 + i];
            float4 bv = *reinterpret_cast<float4*>(&Bs[kk][tx * 4]);
            float b[4] = {bv.x, bv.y, bv.z, bv.w};
#pragma unroll
            for (int i = 0; i < 8; i++)
#pragma unroll
                for (int j = 0; j < 4; j++) acc[i][j] = fmaf(a[i], b[j], acc[i][j]);
        }
        __syncthreads();
    }

#pragma unroll
    for (int i = 0; i < 8; i++) {
        int gr = row0 + ty * 8 + i;
        if (gr < nrows) {
            float4 v = make_float4(acc[i][0], acc[i][1], acc[i][2], acc[i][3]);
            *reinterpret_cast<float4*>(&g_xw[(size_t)gr * DOUT + tx * 4]) = v;
        }
    }
}

// ---------------- 2) per-node attention logits ----------------------------
__global__ void k_att(const float* __restrict__ att_src,
                      const float* __restrict__ att_dst, int n) {
    int row = blockIdx.x * (blockDim.x >> 5) + (threadIdx.x >> 5);
    int l = threadIdx.x & 31;
    if (row >= n) return;
    float4 v = *reinterpret_cast<const float4*>(&g_xw[(size_t)row * DOUT + l * 4]);
    float4 as = *reinterpret_cast<const float4*>(att_src + l * 4);
    float4 ad = *reinterpret_cast<const float4*>(att_dst + l * 4);
    float s = v.x * as.x + v.y * as.y + v.z * as.z + v.w * as.w;
    float d = v.x * ad.x + v.y * ad.y + v.z * ad.z + v.w * ad.w;
#pragma unroll
    for (int off = 16; off > 0; off >>= 1) {
        s += __shfl_xor_sync(0xFFFFFFFFu, s, off);
        d += __shfl_xor_sync(0xFFFFFFFFu, d, off);
    }
    if (l == 0) { g_asrc[row] = s; g_adst[row] = d; }
}

// ---------------- 3) edge pass 1: e = lrelu(...), segment max -------------
__global__ void k_edge_max(const int* __restrict__ ei, int E, int EE) {
    int i = blockIdx.x * blockDim.x + threadIdx.x;
    if (i >= EE) return;
    int is64 = g_is64;
    int s, d;
    if (i < E) { s = edge_src(ei, i, is64); d = edge_dst(ei, i, E, is64); }
    else       { s = d = i - E; }
    float v = g_asrc[s] + g_adst[d];
    v = (v > 0.0f) ? v : NEG_SLOPE * v;
    g_e[i] = v;
    atomicMax(&g_mkey[d], fkey(v));
}

// ---------------- 4) edge pass 2: exp(e - m), segment sum -----------------
__global__ void k_edge_exp(const int* __restrict__ ei, int E, int EE) {
    int i = blockIdx.x * blockDim.x + threadIdx.x;
    if (i >= EE) return;
    int d = (i < E) ? edge_dst(ei, i, E, g_is64) : (i - E);
    float m = keyf(g_mkey[d]);
    float ex = __expf(g_e[i] - m);
    g_e[i] = ex;
    atomicAdd(&g_denom[d], ex);
}

// ---------------- 5) aggregation: out[dst] += xw[src] * alpha -------------
__global__ __launch_bounds__(256)
void k_aggregate(const int* __restrict__ ei, float* __restrict__ out,
                 int E, int EE) {
    long long gid = (long long)blockIdx.x * blockDim.x + threadIdx.x;
    long long total = (long long)EE * 32;
    if (gid >= total) return;
    int e = (int)(gid >> 5);
    int l = (int)(gid & 31);
    int is64 = g_is64;
    int s, d;
    if (e < E) { s = edge_src(ei, e, is64); d = edge_dst(ei, e, E, is64); }
    else       { s = d = e - E; }
    float alpha = g_e[e] / g_denom[d];
    float4 v = *reinterpret_cast<const float4*>(&g_xw[(size_t)s * DOUT + l * 4]);
    float* p = out + (size_t)d * DOUT + l * 4;
    atomicAdd(p + 0, v.x * alpha);
    atomicAdd(p + 1, v.y * alpha);
    atomicAdd(p + 2, v.z * alpha);
    atomicAdd(p + 3, v.w * alpha);
}

// ---------------- 6) epilogue: out = elu(out + bias) ----------------------
__global__ void k_final(float* __restrict__ out, const float* __restrict__ bias,
                        int n) {
    int i = blockIdx.x * blockDim.x + threadIdx.x;
    int total = n * DOUT;
    if (i >= total) return;
    float v = out[i] + bias[i & (DOUT - 1)];
    out[i] = (v > 0.0f) ? v : expm1f(v);
}

// ---------------- launch ---------------------------------------------------
extern "C" void kernel_launch(void* const* d_in, const int* in_sizes, int n_in,
                              void* d_out, int out_size) {
    const float* x    = (const float*)d_in[0];
    const int*   ei   = (const int*)d_in[1];    // int32 words (int64 auto-detected)
    const float* W    = (const float*)d_in[2];
    const float* asv  = (const float*)d_in[3];
    const float* adv  = (const float*)d_in[4];
    const float* bias = (const float*)d_in[5];
    float* out = (float*)d_out;

    int n  = in_sizes[0] / DIN;     // 50000
    int E  = in_sizes[1] / 2;       // 800000 (element count is 2E either way)
    int EE = E + n;                 // edges + self loops

    int t = 256;
    k_detect<<<1, 32>>>(ei);
    k_init<<<(n * DOUT + t - 1) / t, t>>>(out, n);
    k_gemm<<<(n + 63) / 64, 256>>>(x, W, n);
    k_att<<<(n + 7) / 8, 256>>>(asv, adv, n);                 // 8 warps/block
    k_edge_max<<<(EE + t - 1) / t, t>>>(ei, E, EE);
    k_edge_exp<<<(EE + t - 1) / t, t>>>(ei, E, EE);
    long long aggw = (long long)EE * 32;
    k_aggregate<<<(int)((aggw + t - 1) / t), t>>>(ei, out, E, EE);
    k_final<<<(n * DOUT + t - 1) / t, t>>>(out, bias, n);
}

// round 7
// speedup vs baseline: 1.6351x; 1.6351x over previous
#include <cuda_runtime.h>
#include <cuda_bf16.h>

// Problem constants (fixed by the dataset)
#define NMAX 50000
#define EMAX 800000
#define EEMAX (NMAX + EMAX)
#define DOUT 128
#define DIN 128
#define NEG_SLOPE 0.2f

// ---------------- scratch (device globals; no allocation allowed) ----------
__device__ float        g_xw[NMAX * DOUT];   // 25.6 MB
__device__ float        g_asrc[NMAX];
__device__ float        g_adst[NMAX];
__device__ unsigned int g_mkey[NMAX];        // ordered-int max keys
__device__ float        g_denom[NMAX];
__device__ float        g_e[EEMAX];          // e, then overwritten by exp(e-m)
__device__ int          g_is64;              // edge_index stored as int64?

// ---------------- float <-> monotone unsigned key (for atomicMax) ----------
__device__ __forceinline__ unsigned int fkey(float f) {
    unsigned int u = __float_as_uint(f);
    return u ^ ((u & 0x80000000u) ? 0xFFFFFFFFu : 0x80000000u);
}
__device__ __forceinline__ float keyf(unsigned int k) {
    unsigned int u = (k & 0x80000000u) ? (k ^ 0x80000000u) : ~k;
    return __uint_as_float(u);
}

// ---------------- edge-index decoding (int32 vs int64 buffers) -------------
__global__ void k_detect(const int* __restrict__ w) {
    if (threadIdx.x == 0 && blockIdx.x == 0) {
        int odd_or = 0;
#pragma unroll
        for (int j = 0; j < 64; j++) odd_or |= w[2 * j + 1];
        g_is64 = (odd_or == 0) ? 1 : 0;
    }
}
__device__ __forceinline__ int edge_src(const int* w, int i, int is64) {
    return is64 ? w[2 * i] : w[i];
}
__device__ __forceinline__ int edge_dst(const int* w, int i, int E, int is64) {
    return is64 ? w[2 * (E + i)] : w[E + i];
}

// ---------------- 0) init: zero out accumulator + per-node state ----------
__global__ void k_init(float* __restrict__ out, int n) {
    int i = blockIdx.x * blockDim.x + threadIdx.x;
    int total = n * DOUT;
    if (i < total) out[i] = 0.0f;
    if (i < n) { g_mkey[i] = 0u; g_denom[i] = 0.0f; }
}

// -------- 1) GEMM: xw = x @ W  (BM=64, BK=16, 8x4/thread) + fused att -----
__global__ __launch_bounds__(256, 3)
void k_gemm(const float* __restrict__ x, const float* __restrict__ W,
            const float* __restrict__ att_src, const float* __restrict__ att_dst,
            int nrows) {
    __shared__ float As[16][64];    // [k][row]
    __shared__ float Bs[16][DOUT];  // [k][col]

    int tid = threadIdx.x;
    int row0 = blockIdx.x * 64;
    int ty = tid >> 5;   // 0..7  -> rows ty*8 .. ty*8+7
    int tx = tid & 31;   // 0..31 -> cols tx*4 .. tx*4+3

    float acc[8][4];
#pragma unroll
    for (int i = 0; i < 8; i++)
#pragma unroll
        for (int j = 0; j < 4; j++) acc[i][j] = 0.0f;

    int arow = tid >> 2;       // 0..63
    int kq = tid & 3;          // float4 index along K

    for (int k0 = 0; k0 < DIN; k0 += 16) {
        float4 av = make_float4(0.f, 0.f, 0.f, 0.f);
        int gr = row0 + arow;
        if (gr < nrows)
            av = *reinterpret_cast<const float4*>(x + (size_t)gr * DIN + k0 + 4 * kq);
        As[4 * kq + 0][arow] = av.x;
        As[4 * kq + 1][arow] = av.y;
        As[4 * kq + 2][arow] = av.z;
        As[4 * kq + 3][arow] = av.w;
#pragma unroll
        for (int i = 0; i < 2; i++) {
            int fi = tid + i * 256;
            int bk = fi >> 5;
            int bc = (fi & 31) * 4;
            float4 bv = *reinterpret_cast<const float4*>(W + (size_t)(k0 + bk) * DOUT + bc);
            *reinterpret_cast<float4*>(&Bs[bk][bc]) = bv;
        }
        __syncthreads();

#pragma unroll
        for (int kk = 0; kk < 16; kk++) {
            float a[8];
#pragma unroll
            for (int i = 0; i < 8; i++) a[i] = As[kk][ty * 8 + i];
            float4 bv = *reinterpret_cast<float4*>(&Bs[kk][tx * 4]);
            float b[4] = {bv.x, bv.y, bv.z, bv.w};
#pragma unroll
            for (int i = 0; i < 8; i++)
#pragma unroll
                for (int j = 0; j < 4; j++) acc[i][j] = fmaf(a[i], b[j], acc[i][j]);
        }
        __syncthreads();
    }

    // store xw + fused per-node attention logits (warp covers full rows)
    float4 asv = *reinterpret_cast<const float4*>(att_src + tx * 4);
    float4 adv = *reinterpret_cast<const float4*>(att_dst + tx * 4);
#pragma unroll
    for (int i = 0; i < 8; i++) {
        int gr = row0 + ty * 8 + i;
        float s = acc[i][0] * asv.x + acc[i][1] * asv.y + acc[i][2] * asv.z + acc[i][3] * asv.w;
        float d = acc[i][0] * adv.x + acc[i][1] * adv.y + acc[i][2] * adv.z + acc[i][3] * adv.w;
#pragma unroll
        for (int off = 16; off > 0; off >>= 1) {
            s += __shfl_xor_sync(0xFFFFFFFFu, s, off);
            d += __shfl_xor_sync(0xFFFFFFFFu, d, off);
        }
        if (gr < nrows) {
            float4 v = make_float4(acc[i][0], acc[i][1], acc[i][2], acc[i][3]);
            *reinterpret_cast<float4*>(&g_xw[(size_t)gr * DOUT + tx * 4]) = v;
            if (tx == 0) { g_asrc[gr] = s; g_adst[gr] = d; }
        }
    }
}

// ---------------- 3) edge pass 1: e = lrelu(...), segment max -------------
__global__ void k_edge_max(const int* __restrict__ ei, int E, int EE) {
    int i = blockIdx.x * blockDim.x + threadIdx.x;
    if (i >= EE) return;
    int is64 = g_is64;
    int s, d;
    if (i < E) { s = edge_src(ei, i, is64); d = edge_dst(ei, i, E, is64); }
    else       { s = d = i - E; }
    float v = g_asrc[s] + g_adst[d];
    v = (v > 0.0f) ? v : NEG_SLOPE * v;
    g_e[i] = v;
    atomicMax(&g_mkey[d], fkey(v));
}

// ---------------- 4) edge pass 2: exp(e - m), segment sum -----------------
__global__ void k_edge_exp(const int* __restrict__ ei, int E, int EE) {
    int i = blockIdx.x * blockDim.x + threadIdx.x;
    if (i >= EE) return;
    int d = (i < E) ? edge_dst(ei, i, E, g_is64) : (i - E);
    float m = keyf(g_mkey[d]);
    float ex = __expf(g_e[i] - m);
    g_e[i] = ex;
    atomicAdd(&g_denom[d], ex);
}

// ---------------- 5) aggregation: out[dst] += xw[src] * alpha -------------
// one warp per edge; lane 0 resolves indices + alpha, broadcast by shuffle;
// one vector red.global.add.v4.f32 per lane (16B) -> 32 per edge.
__global__ __launch_bounds__(256)
void k_aggregate(const int* __restrict__ ei, float* __restrict__ out,
                 int E, int EE) {
    int e = blockIdx.x * (blockDim.x >> 5) + (threadIdx.x >> 5);
    if (e >= EE) return;
    int l = threadIdx.x & 31;
    int s = 0, d = 0;
    float alpha = 0.0f;
    if (l == 0) {
        int is64 = g_is64;
        if (e < E) { s = edge_src(ei, e, is64); d = edge_dst(ei, e, E, is64); }
        else       { s = d = e - E; }
        alpha = g_e[e] / g_denom[d];
    }
    s = __shfl_sync(0xFFFFFFFFu, s, 0);
    d = __shfl_sync(0xFFFFFFFFu, d, 0);
    alpha = __shfl_sync(0xFFFFFFFFu, alpha, 0);
    float4 v = *reinterpret_cast<const float4*>(&g_xw[(size_t)s * DOUT + l * 4]);
    v.x *= alpha; v.y *= alpha; v.z *= alpha; v.w *= alpha;
    float* p = out + (size_t)d * DOUT + l * 4;
    asm volatile("red.global.add.v4.f32 [%0], {%1,%2,%3,%4};"
                 :: "l"(p), "f"(v.x), "f"(v.y), "f"(v.z), "f"(v.w)
                 : "memory");
}

// ---------------- 6) epilogue: out = elu(out + bias) ----------------------
__global__ void k_final(float* __restrict__ out, const float* __restrict__ bias,
                        int n) {
    int i = blockIdx.x * blockDim.x + threadIdx.x;
    int total = n * DOUT;
    if (i >= total) return;
    float v = out[i] + bias[i & (DOUT - 1)];
    out[i] = (v > 0.0f) ? v : expm1f(v);
}

// ---------------- launch ---------------------------------------------------
extern "C" void kernel_launch(void* const* d_in, const int* in_sizes, int n_in,
                              void* d_out, int out_size) {
    const float* x    = (const float*)d_in[0];
    const int*   ei   = (const int*)d_in[1];    // int32 words (int64 auto-detected)
    const float* W    = (const float*)d_in[2];
    const float* asv  = (const float*)d_in[3];
    const float* adv  = (const float*)d_in[4];
    const float* bias = (const float*)d_in[5];
    float* out = (float*)d_out;

    int n  = in_sizes[0] / DIN;     // 50000
    int E  = in_sizes[1] / 2;       // 800000 (element count is 2E either way)
    int EE = E + n;                 // edges + self loops

    int t = 256;
    k_detect<<<1, 32>>>(ei);
    k_init<<<(n * DOUT + t - 1) / t, t>>>(out, n);
    k_gemm<<<(n + 63) / 64, 256>>>(x, W, asv, adv, n);
    k_edge_max<<<(EE + t - 1) / t, t>>>(ei, E, EE);
    k_edge_exp<<<(EE + t - 1) / t, t>>>(ei, E, EE);
    k_aggregate<<<(EE + 7) / 8, t>>>(ei, out, E, EE);   // 8 warps/block, 1 edge/warp
    k_final<<<(n * DOUT + t - 1) / t, t>>>(out, bias, n);
}

// round 10
// speedup vs baseline: 1.8058x; 1.1044x over previous
#include <cuda_runtime.h>
#include <cuda_bf16.h>

// Problem constants (fixed by the dataset)
#define NMAX 50000
#define EMAX 800000
#define DOUT 128
#define DIN 128
#define NEG_SLOPE 0.2f

// ---------------- scratch (device globals; no allocation allowed) ----------
__device__ float g_xw[NMAX * DOUT];       // 25.6 MB
__device__ float g_asrc[NMAX];
__device__ float g_adst[NMAX];
__device__ int   g_cnt[NMAX];             // per-dst edge count (real edges only)
__device__ int   g_rowstart[NMAX + 1];    // CSR row offsets
__device__ int   g_cursor[NMAX];          // scatter cursors
__device__ int   g_csr_src[EMAX];         // CSR: src node per edge, grouped by dst
__device__ int   g_is64;                  // edge_index stored as int64?

// ---------------- edge-index decoding (int32 vs int64 buffers) -------------
__global__ void k_detect(const int* __restrict__ w) {
    if (threadIdx.x == 0 && blockIdx.x == 0) {
        int odd_or = 0;
#pragma unroll
        for (int j = 0; j < 64; j++) odd_or |= w[2 * j + 1];
        g_is64 = (odd_or == 0) ? 1 : 0;
    }
}
__device__ __forceinline__ int edge_src(const int* w, int i, int is64) {
    return is64 ? w[2 * i] : w[i];
}
__device__ __forceinline__ int edge_dst(const int* w, int i, int E, int is64) {
    return is64 ? w[2 * (E + i)] : w[E + i];
}

// ---------------- 0) zero histogram ----------------------------------------
__global__ void k_zero(int n) {
    int i = blockIdx.x * blockDim.x + threadIdx.x;
    if (i < n) g_cnt[i] = 0;
}

// -------- 1) GEMM: xw = x @ W  (BM=64, BK=16, 8x4/thread) + fused att -----
__global__ __launch_bounds__(256, 3)
void k_gemm(const float* __restrict__ x, const float* __restrict__ W,
            const float* __restrict__ att_src, const float* __restrict__ att_dst,
            int nrows) {
    __shared__ float As[16][64];    // [k][row]
    __shared__ float Bs[16][DOUT];  // [k][col]

    int tid = threadIdx.x;
    int row0 = blockIdx.x * 64;
    int ty = tid >> 5;
    int tx = tid & 31;

    float acc[8][4];
#pragma unroll
    for (int i = 0; i < 8; i++)
#pragma unroll
        for (int j = 0; j < 4; j++) acc[i][j] = 0.0f;

    int arow = tid >> 2;
    int kq = tid & 3;

    for (int k0 = 0; k0 < DIN; k0 += 16) {
        float4 av = make_float4(0.f, 0.f, 0.f, 0.f);
        int gr = row0 + arow;
        if (gr < nrows)
            av = *reinterpret_cast<const float4*>(x + (size_t)gr * DIN + k0 + 4 * kq);
        As[4 * kq + 0][arow] = av.x;
        As[4 * kq + 1][arow] = av.y;
        As[4 * kq + 2][arow] = av.z;
        As[4 * kq + 3][arow] = av.w;
#pragma unroll
        for (int i = 0; i < 2; i++) {
            int fi = tid + i * 256;
            int bk = fi >> 5;
            int bc = (fi & 31) * 4;
            float4 bv = *reinterpret_cast<const float4*>(W + (size_t)(k0 + bk) * DOUT + bc);
            *reinterpret_cast<float4*>(&Bs[bk][bc]) = bv;
        }
        __syncthreads();

#pragma unroll
        for (int kk = 0; kk < 16; kk++) {
            float a[8];
#pragma unroll
            for (int i = 0; i < 8; i++) a[i] = As[kk][ty * 8 + i];
            float4 bv = *reinterpret_cast<float4*>(&Bs[kk][tx * 4]);
            float b[4] = {bv.x, bv.y, bv.z, bv.w};
#pragma unroll
            for (int i = 0; i < 8; i++)
#pragma unroll
                for (int j = 0; j < 4; j++) acc[i][j] = fmaf(a[i], b[j], acc[i][j]);
        }
        __syncthreads();
    }

    float4 asv = *reinterpret_cast<const float4*>(att_src + tx * 4);
    float4 adv = *reinterpret_cast<const float4*>(att_dst + tx * 4);
#pragma unroll
    for (int i = 0; i < 8; i++) {
        int gr = row0 + ty * 8 + i;
        float s = acc[i][0] * asv.x + acc[i][1] * asv.y + acc[i][2] * asv.z + acc[i][3] * asv.w;
        float d = acc[i][0] * adv.x + acc[i][1] * adv.y + acc[i][2] * adv.z + acc[i][3] * adv.w;
#pragma unroll
        for (int off = 16; off > 0; off >>= 1) {
            s += __shfl_xor_sync(0xFFFFFFFFu, s, off);
            d += __shfl_xor_sync(0xFFFFFFFFu, d, off);
        }
        if (gr < nrows) {
            float4 v = make_float4(acc[i][0], acc[i][1], acc[i][2], acc[i][3]);
            *reinterpret_cast<float4*>(&g_xw[(size_t)gr * DOUT + tx * 4]) = v;
            if (tx == 0) { g_asrc[gr] = s; g_adst[gr] = d; }
        }
    }
}

// ---------------- 2) histogram of destinations ------------------------------
__global__ void k_count(const int* __restrict__ ei, int E) {
    int i = blockIdx.x * blockDim.x + threadIdx.x;
    if (i >= E) return;
    int d = edge_dst(ei, i, E, g_is64);
    atomicAdd(&g_cnt[d], 1);
}

// ---------------- 3) exclusive scan (single block, chunked) -----------------
__global__ __launch_bounds__(1024)
void k_scan(int n) {
    __shared__ int sh[1024];
    int t = threadIdx.x;
    int C = (n + 1023) >> 10;            // elems per thread
    int base = t * C;
    int s = 0;
    for (int i = 0; i < C; i++) {
        int idx = base + i;
        if (idx < n) s += g_cnt[idx];
    }
    sh[t] = s;
    __syncthreads();
    for (int off = 1; off < 1024; off <<= 1) {
        int v = (t >= off) ? sh[t - off] : 0;
        __syncthreads();
        sh[t] += v;
        __syncthreads();
    }
    int run = sh[t] - s;                 // exclusive prefix for this chunk
    for (int i = 0; i < C; i++) {
        int idx = base + i;
        if (idx < n) {
            g_rowstart[idx] = run;
            g_cursor[idx] = run;
            run += g_cnt[idx];
        }
    }
    if (t == 1023) g_rowstart[n] = sh[1023];
}

// ---------------- 4) scatter edges into CSR ---------------------------------
__global__ void k_scatter(const int* __restrict__ ei, int E) {
    int i = blockIdx.x * blockDim.x + threadIdx.x;
    if (i >= E) return;
    int is64 = g_is64;
    int s = edge_src(ei, i, is64);
    int d = edge_dst(ei, i, E, is64);
    int pos = atomicAdd(&g_cursor[d], 1);
    g_csr_src[pos] = s;
}

// ------ 5) per-node softmax + aggregation + bias + ELU (one warp/node) ------
__global__ __launch_bounds__(256)
void k_node(float* __restrict__ out, const float* __restrict__ bias, int n) {
    int d = blockIdx.x * 8 + (threadIdx.x >> 5);
    if (d >= n) return;
    int l = threadIdx.x & 31;

    int row = g_rowstart[d];
    int end = g_rowstart[d + 1];
    float adv = g_adst[d];

    // phase 1: denom = sum of exp(lrelu(asrc[s] + adst[d])), incl. self loop
    float es = g_asrc[d] + adv;
    es = (es > 0.0f) ? es : NEG_SLOPE * es;
    float ex_self = __expf(es);
    float sum = 0.0f;
    for (int j = row + l; j < end; j += 32) {
        int s = g_csr_src[j];
        float e = g_asrc[s] + adv;
        e = (e > 0.0f) ? e : NEG_SLOPE * e;
        sum += __expf(e);
    }
#pragma unroll
    for (int off = 16; off > 0; off >>= 1)
        sum += __shfl_xor_sync(0xFFFFFFFFu, sum, off);
    float inv = 1.0f / (sum + ex_self);

    // phase 2: acc = sum alpha_j * xw[s_j][:], lanes cover 4 cols each
    float4 acc;
    {
        float a = ex_self * inv;
        float4 v = *reinterpret_cast<const float4*>(&g_xw[(size_t)d * DOUT + l * 4]);
        acc.x = a * v.x; acc.y = a * v.y; acc.z = a * v.z; acc.w = a * v.w;
    }
    for (int j = row; j < end; j++) {
        int s = g_csr_src[j];                  // broadcast load
        float e = g_asrc[s] + adv;             // broadcast load
        e = (e > 0.0f) ? e : NEG_SLOPE * e;
        float a = __expf(e) * inv;
        float4 v = *reinterpret_cast<const float4*>(&g_xw[(size_t)s * DOUT + l * 4]);
        acc.x = fmaf(a, v.x, acc.x);
        acc.y = fmaf(a, v.y, acc.y);
        acc.z = fmaf(a, v.z, acc.z);
        acc.w = fmaf(a, v.w, acc.w);
    }

    float4 b = *reinterpret_cast<const float4*>(bias + l * 4);
    acc.x += b.x; acc.y += b.y; acc.z += b.z; acc.w += b.w;
    acc.x = (acc.x > 0.0f) ? acc.x : expm1f(acc.x);
    acc.y = (acc.y > 0.0f) ? acc.y : expm1f(acc.y);
    acc.z = (acc.z > 0.0f) ? acc.z : expm1f(acc.z);
    acc.w = (acc.w > 0.0f) ? acc.w : expm1f(acc.w);
    *reinterpret_cast<float4*>(&out[(size_t)d * DOUT + l * 4]) = acc;
}

// ---------------- launch ---------------------------------------------------
extern "C" void kernel_launch(void* const* d_in, const int* in_sizes, int n_in,
                              void* d_out, int out_size) {
    const float* x    = (const float*)d_in[0];
    const int*   ei   = (const int*)d_in[1];    // int32 words (int64 auto-detected)
    const float* W    = (const float*)d_in[2];
    const float* asv  = (const float*)d_in[3];
    const float* adv  = (const float*)d_in[4];
    const float* bias = (const float*)d_in[5];
    float* out = (float*)d_out;

    int n = in_sizes[0] / DIN;      // 50000
    int E = in_sizes[1] / 2;        // 800000

    int t = 256;
    k_detect<<<1, 32>>>(ei);
    k_zero<<<(n + t - 1) / t, t>>>(n);
    k_gemm<<<(n + 63) / 64, 256>>>(x, W, asv, adv, n);
    k_count<<<(E + t - 1) / t, t>>>(ei, E);
    k_scan<<<1, 1024>>>(n);
    k_scatter<<<(E + t - 1) / t, t>>>(ei, E);
    k_node<<<(n + 7) / 8, t>>>(out, bias, n);
}

// round 11
// speedup vs baseline: 1.8104x; 1.0026x over previous
#include <cuda_runtime.h>
#include <cuda_bf16.h>

// Problem constants (fixed by the dataset)
#define NMAX 50000
#define EMAX 800000
#define DOUT 128
#define DIN 128
#define NEG_SLOPE 0.2f
#define WCAP 128   // per-warp staged edges in k_node

// ---------------- scratch (device globals; no allocation allowed) ----------
__device__ float g_xw[NMAX * DOUT];       // 25.6 MB
__device__ float g_asrc[NMAX];
__device__ float g_adst[NMAX];
__device__ int   g_cnt[NMAX];             // per-dst edge count (real edges only)
__device__ int   g_rowstart[NMAX + 1];    // CSR row offsets
__device__ int   g_cursor[NMAX];          // scatter cursors
__device__ int   g_csr_src[EMAX];         // CSR: src node per edge, grouped by dst
__device__ int   g_is64;                  // edge_index stored as int64?

// ---------------- packed f32x2 helpers --------------------------------------
__device__ __forceinline__ unsigned long long pack2(float x, float y) {
    unsigned long long r;
    asm("mov.b64 %0, {%1, %2};" : "=l"(r) : "f"(x), "f"(y));
    return r;
}
__device__ __forceinline__ void unpack2(unsigned long long v, float& x, float& y) {
    asm("mov.b64 {%0, %1}, %2;" : "=f"(x), "=f"(y) : "l"(v));
}
__device__ __forceinline__ void fma2(unsigned long long& d,
                                     unsigned long long a, unsigned long long b) {
    asm("fma.rn.f32x2 %0, %1, %2, %0;" : "+l"(d) : "l"(a), "l"(b));
}

// ---------------- edge-index decoding (int32 vs int64 buffers) -------------
__device__ __forceinline__ int edge_src(const int* w, int i, int is64) {
    return is64 ? w[2 * i] : w[i];
}
__device__ __forceinline__ int edge_dst(const int* w, int i, int E, int is64) {
    return is64 ? w[2 * (E + i)] : w[E + i];
}

// ---------------- 0) detect dtype + zero histogram (merged) ----------------
__global__ void k_detect_zero(const int* __restrict__ w, int n) {
    int i = blockIdx.x * blockDim.x + threadIdx.x;
    if (i < n) g_cnt[i] = 0;
    if (i == 0) {
        int odd_or = 0;
#pragma unroll
        for (int j = 0; j < 64; j++) odd_or |= w[2 * j + 1];
        g_is64 = (odd_or == 0) ? 1 : 0;
    }
}

// -------- 1) GEMM: xw = x @ W  (BM=128, BK=16, 8x8/thread, f32x2 FMA) ------
//            + fused per-node attention logits
__global__ __launch_bounds__(256, 2)
void k_gemm(const float* __restrict__ x, const float* __restrict__ W,
            const float* __restrict__ att_src, const float* __restrict__ att_dst,
            int nrows) {
    __shared__ float As[16][128];   // [k][row]
    __shared__ float Bs[16][DOUT];  // [k][col]

    int tid = threadIdx.x;
    int row0 = blockIdx.x * 128;
    int ty = tid >> 4;    // 0..15 -> rows ty*8 .. ty*8+7
    int tx = tid & 15;    // 0..15 -> cols tx*8 .. tx*8+7

    // acc2[i][jp]: row i (0..7), col pair jp (0..3) -> cols tx*8+2*jp, +1
    unsigned long long acc2[8][4];
#pragma unroll
    for (int i = 0; i < 8; i++)
#pragma unroll
        for (int j = 0; j < 4; j++) acc2[i][j] = 0ULL;

    for (int k0 = 0; k0 < DIN; k0 += 16) {
        // stage A tile (128 x 16) transposed: 512 float4, 2 per thread
#pragma unroll
        for (int p = 0; p < 2; p++) {
            int fi = tid + 256 * p;
            int arow = fi >> 2;        // 0..127
            int kq = fi & 3;           // float4 along K
            float4 av = make_float4(0.f, 0.f, 0.f, 0.f);
            int gr = row0 + arow;
            if (gr < nrows)
                av = *reinterpret_cast<const float4*>(x + (size_t)gr * DIN + k0 + 4 * kq);
            As[4 * kq + 0][arow] = av.x;
            As[4 * kq + 1][arow] = av.y;
            As[4 * kq + 2][arow] = av.z;
            As[4 * kq + 3][arow] = av.w;
        }
        // stage B tile (16 x 128): 512 float4, 2 per thread
#pragma unroll
        for (int p = 0; p < 2; p++) {
            int fi = tid + 256 * p;
            int bk = fi >> 5;
            int bc = (fi & 31) * 4;
            float4 bv = *reinterpret_cast<const float4*>(W + (size_t)(k0 + bk) * DOUT + bc);
            *reinterpret_cast<float4*>(&Bs[bk][bc]) = bv;
        }
        __syncthreads();

#pragma unroll
        for (int kk = 0; kk < 16; kk++) {
            // b pairs: 4 x u64 directly from smem
            ulonglong2 b01 = *reinterpret_cast<ulonglong2*>(&Bs[kk][tx * 8]);
            ulonglong2 b23 = *reinterpret_cast<ulonglong2*>(&Bs[kk][tx * 8 + 4]);
            unsigned long long bp[4] = {b01.x, b01.y, b23.x, b23.y};
            float4 a03 = *reinterpret_cast<float4*>(&As[kk][ty * 8]);
            float4 a47 = *reinterpret_cast<float4*>(&As[kk][ty * 8 + 4]);
            float a[8] = {a03.x, a03.y, a03.z, a03.w, a47.x, a47.y, a47.z, a47.w};
#pragma unroll
            for (int i = 0; i < 8; i++) {
                unsigned long long ap = pack2(a[i], a[i]);
#pragma unroll
                for (int j = 0; j < 4; j++) fma2(acc2[i][j], ap, bp[j]);
            }
        }
        __syncthreads();
    }

    // epilogue: store xw + fused attention logits
    float4 as0 = *reinterpret_cast<const float4*>(att_src + tx * 8);
    float4 as1 = *reinterpret_cast<const float4*>(att_src + tx * 8 + 4);
    float4 ad0 = *reinterpret_cast<const float4*>(att_dst + tx * 8);
    float4 ad1 = *reinterpret_cast<const float4*>(att_dst + tx * 8 + 4);
#pragma unroll
    for (int i = 0; i < 8; i++) {
        float c[8];
        unpack2(acc2[i][0], c[0], c[1]);
        unpack2(acc2[i][1], c[2], c[3]);
        unpack2(acc2[i][2], c[4], c[5]);
        unpack2(acc2[i][3], c[6], c[7]);
        int gr = row0 + ty * 8 + i;

        float s = c[0]*as0.x + c[1]*as0.y + c[2]*as0.z + c[3]*as0.w
                + c[4]*as1.x + c[5]*as1.y + c[6]*as1.z + c[7]*as1.w;
        float d = c[0]*ad0.x + c[1]*ad0.y + c[2]*ad0.z + c[3]*ad0.w
                + c[4]*ad1.x + c[5]*ad1.y + c[6]*ad1.z + c[7]*ad1.w;
        // reduce across the 16 lanes sharing this ty (xor stays within half)
#pragma unroll
        for (int off = 8; off > 0; off >>= 1) {
            s += __shfl_xor_sync(0xFFFFFFFFu, s, off);
            d += __shfl_xor_sync(0xFFFFFFFFu, d, off);
        }
        if (gr < nrows) {
            *reinterpret_cast<float4*>(&g_xw[(size_t)gr * DOUT + tx * 8]) =
                make_float4(c[0], c[1], c[2], c[3]);
            *reinterpret_cast<float4*>(&g_xw[(size_t)gr * DOUT + tx * 8 + 4]) =
                make_float4(c[4], c[5], c[6], c[7]);
            if (tx == 0) { g_asrc[gr] = s; g_adst[gr] = d; }
        }
    }
}

// ---------------- 2) histogram of destinations ------------------------------
__global__ void k_count(const int* __restrict__ ei, int E) {
    int i0 = (blockIdx.x * blockDim.x + threadIdx.x) * 4;
    int is64 = g_is64;
#pragma unroll
    for (int r = 0; r < 4; r++) {
        int i = i0 + r;
        if (i < E) atomicAdd(&g_cnt[edge_dst(ei, i, E, is64)], 1);
    }
}

// ---------------- 3) exclusive scan (single block, chunked) -----------------
__global__ __launch_bounds__(1024)
void k_scan(int n) {
    __shared__ int sh[1024];
    int t = threadIdx.x;
    int C = (n + 1023) >> 10;
    int base = t * C;
    int s = 0;
    for (int i = 0; i < C; i++) {
        int idx = base + i;
        if (idx < n) s += g_cnt[idx];
    }
    sh[t] = s;
    __syncthreads();
    for (int off = 1; off < 1024; off <<= 1) {
        int v = (t >= off) ? sh[t - off] : 0;
        __syncthreads();
        sh[t] += v;
        __syncthreads();
    }
    int run = sh[t] - s;
    for (int i = 0; i < C; i++) {
        int idx = base + i;
        if (idx < n) {
            g_rowstart[idx] = run;
            g_cursor[idx] = run;
            run += g_cnt[idx];
        }
    }
    if (t == 1023) g_rowstart[n] = sh[1023];
}

// ---------------- 4) scatter edges into CSR ---------------------------------
__global__ void k_scatter(const int* __restrict__ ei, int E) {
    int i0 = (blockIdx.x * blockDim.x + threadIdx.x) * 4;
    int is64 = g_is64;
#pragma unroll
    for (int r = 0; r < 4; r++) {
        int i = i0 + r;
        if (i < E) {
            int s = edge_src(ei, i, is64);
            int d = edge_dst(ei, i, E, is64);
            int pos = atomicAdd(&g_cursor[d], 1);
            g_csr_src[pos] = s;
        }
    }
}

// ------ 5) per-node softmax + aggregation + bias + ELU (one warp/node) ------
__global__ __launch_bounds__(256)
void k_node(float* __restrict__ out, const float* __restrict__ bias, int n) {
    __shared__ int   sh_src[8][WCAP];
    __shared__ float sh_ex[8][WCAP];

    int w = threadIdx.x >> 5;
    int d = blockIdx.x * 8 + w;
    if (d >= n) return;
    int l = threadIdx.x & 31;

    int row = g_rowstart[d];
    int end = g_rowstart[d + 1];
    int deg = end - row;
    float adv = g_adst[d];

    // phase 1: denom + stage (src, exp) into smem
    float es = g_asrc[d] + adv;
    es = (es > 0.0f) ? es : NEG_SLOPE * es;
    float ex_self = __expf(es);
    float sum = 0.0f;
    for (int j = l; j < deg; j += 32) {
        int s = g_csr_src[row + j];
        float e = g_asrc[s] + adv;
        e = (e > 0.0f) ? e : NEG_SLOPE * e;
        float ex = __expf(e);
        sum += ex;
        if (j < WCAP) { sh_src[w][j] = s; sh_ex[w][j] = ex; }
    }
#pragma unroll
    for (int off = 16; off > 0; off >>= 1)
        sum += __shfl_xor_sync(0xFFFFFFFFu, sum, off);
    float inv = 1.0f / (sum + ex_self);
    __syncwarp();

    // phase 2: acc = sum alpha_j * xw[s_j][:], lanes cover 4 cols each
    float4 acc;
    {
        float a = ex_self * inv;
        float4 v = *reinterpret_cast<const float4*>(&g_xw[(size_t)d * DOUT + l * 4]);
        acc.x = a * v.x; acc.y = a * v.y; acc.z = a * v.z; acc.w = a * v.w;
    }
    int m = (deg < WCAP) ? deg : WCAP;
    int j = 0;
    for (; j + 4 <= m; j += 4) {
        int s0 = sh_src[w][j + 0], s1 = sh_src[w][j + 1];
        int s2 = sh_src[w][j + 2], s3 = sh_src[w][j + 3];
        float a0 = sh_ex[w][j + 0] * inv, a1 = sh_ex[w][j + 1] * inv;
        float a2 = sh_ex[w][j + 2] * inv, a3 = sh_ex[w][j + 3] * inv;
        float4 v0 = *reinterpret_cast<const float4*>(&g_xw[(size_t)s0 * DOUT + l * 4]);
        float4 v1 = *reinterpret_cast<const float4*>(&g_xw[(size_t)s1 * DOUT + l * 4]);
        float4 v2 = *reinterpret_cast<const float4*>(&g_xw[(size_t)s2 * DOUT + l * 4]);
        float4 v3 = *reinterpret_cast<const float4*>(&g_xw[(size_t)s3 * DOUT + l * 4]);
        acc.x = fmaf(a0, v0.x, acc.x); acc.y = fmaf(a0, v0.y, acc.y);
        acc.z = fmaf(a0, v0.z, acc.z); acc.w = fmaf(a0, v0.w, acc.w);
        acc.x = fmaf(a1, v1.x, acc.x); acc.y = fmaf(a1, v1.y, acc.y);
        acc.z = fmaf(a1, v1.z, acc.z); acc.w = fmaf(a1, v1.w, acc.w);
        acc.x = fmaf(a2, v2.x, acc.x); acc.y = fmaf(a2, v2.y, acc.y);
        acc.z = fmaf(a2, v2.z, acc.z); acc.w = fmaf(a2, v2.w, acc.w);
        acc.x = fmaf(a3, v3.x, acc.x); acc.y = fmaf(a3, v3.y, acc.y);
        acc.z = fmaf(a3, v3.z, acc.z); acc.w = fmaf(a3, v3.w, acc.w);
    }
    for (; j < m; j++) {
        int s = sh_src[w][j];
        float a = sh_ex[w][j] * inv;
        float4 v = *reinterpret_cast<const float4*>(&g_xw[(size_t)s * DOUT + l * 4]);
        acc.x = fmaf(a, v.x, acc.x); acc.y = fmaf(a, v.y, acc.y);
        acc.z = fmaf(a, v.z, acc.z); acc.w = fmaf(a, v.w, acc.w);
    }
    // overflow path (deg > WCAP): recompute from global
    for (int jj = WCAP; jj < deg; jj++) {
        int s = g_csr_src[row + jj];
        float e = g_asrc[s] + adv;
        e = (e > 0.0f) ? e : NEG_SLOPE * e;
        float a = __expf(e) * inv;
        float4 v = *reinterpret_cast<const float4*>(&g_xw[(size_t)s * DOUT + l * 4]);
        acc.x = fmaf(a, v.x, acc.x); acc.y = fmaf(a, v.y, acc.y);
        acc.z = fmaf(a, v.z, acc.z); acc.w = fmaf(a, v.w, acc.w);
    }

    float4 b = *reinterpret_cast<const float4*>(bias + l * 4);
    acc.x += b.x; acc.y += b.y; acc.z += b.z; acc.w += b.w;
    acc.x = (acc.x > 0.0f) ? acc.x : expm1f(acc.x);
    acc.y = (acc.y > 0.0f) ? acc.y : expm1f(acc.y);
    acc.z = (acc.z > 0.0f) ? acc.z : expm1f(acc.z);
    acc.w = (acc.w > 0.0f) ? acc.w : expm1f(acc.w);
    *reinterpret_cast<float4*>(&out[(size_t)d * DOUT + l * 4]) = acc;
}

// ---------------- launch ---------------------------------------------------
extern "C" void kernel_launch(void* const* d_in, const int* in_sizes, int n_in,
                              void* d_out, int out_size) {
    const float* x    = (const float*)d_in[0];
    const int*   ei   = (const int*)d_in[1];    // int32 words (int64 auto-detected)
    const float* W    = (const float*)d_in[2];
    const float* asv  = (const float*)d_in[3];
    const float* adv  = (const float*)d_in[4];
    const float* bias = (const float*)d_in[5];
    float* out = (float*)d_out;

    int n = in_sizes[0] / DIN;      // 50000
    int E = in_sizes[1] / 2;        // 800000

    int t = 256;
    k_detect_zero<<<(n + t - 1) / t, t>>>(ei, n);
    k_gemm<<<(n + 127) / 128, 256>>>(x, W, asv, adv, n);
    k_count<<<(E + 4 * t - 1) / (4 * t), t>>>(ei, E);
    k_scan<<<1, 1024>>>(n);
    k_scatter<<<(E + 4 * t - 1) / (4 * t), t>>>(ei, E);
    k_node<<<(n + 7) / 8, t>>>(out, bias, n);
}

// round 13
// speedup vs baseline: 2.8883x; 1.5954x over previous
#include <cuda_runtime.h>
#include <cuda_bf16.h>

// Problem constants (fixed by the dataset)
#define NMAX 50000
#define EMAX 800000
#define DOUT 128
#define DIN 128
#define NEG_SLOPE 0.2f
#define WCAP 128   // per-warp staged edges in k_node

// ---------------- scratch (device globals; no allocation allowed) ----------
__device__ float g_xw[NMAX * DOUT];       // 25.6 MB
__device__ float g_asrc[NMAX];
__device__ float g_adst[NMAX];
__device__ int   g_cnt[NMAX];             // per-dst edge count (real edges only)
__device__ int   g_rowstart[NMAX + 1];    // CSR row offsets
__device__ int   g_cursor[NMAX];          // scatter cursors
__device__ int   g_csr_src[EMAX];         // CSR: src node per edge, grouped by dst
__device__ int   g_is64;                  // edge_index stored as int64?
__device__ int   g_bsum[64];              // scan: per-block totals
__device__ int   g_boff[64];              // scan: per-block exclusive offsets
__device__ int   g_total;                 // scan: grand total

// ---------------- packed f32x2 helpers --------------------------------------
__device__ __forceinline__ unsigned long long pack2(float x, float y) {
    unsigned long long r;
    asm("mov.b64 %0, {%1, %2};" : "=l"(r) : "f"(x), "f"(y));
    return r;
}
__device__ __forceinline__ void unpack2(unsigned long long v, float& x, float& y) {
    asm("mov.b64 {%0, %1}, %2;" : "=f"(x), "=f"(y) : "l"(v));
}
__device__ __forceinline__ void fma2(unsigned long long& d,
                                     unsigned long long a, unsigned long long b) {
    asm("fma.rn.f32x2 %0, %1, %2, %0;" : "+l"(d) : "l"(a), "l"(b));
}

// ---------------- edge-index decoding (int32 vs int64 buffers) -------------
__device__ __forceinline__ int edge_src(const int* w, int i, int is64) {
    return is64 ? w[2 * i] : w[i];
}
__device__ __forceinline__ int edge_dst(const int* w, int i, int E, int is64) {
    return is64 ? w[2 * (E + i)] : w[E + i];
}

// ---------------- 0) detect dtype + zero histogram (merged) ----------------
__global__ void k_detect_zero(const int* __restrict__ w, int n) {
    int i = blockIdx.x * blockDim.x + threadIdx.x;
    if (i < n) g_cnt[i] = 0;
    if (i == 0) {
        int odd_or = 0;
#pragma unroll
        for (int j = 0; j < 64; j++) odd_or |= w[2 * j + 1];
        g_is64 = (odd_or == 0) ? 1 : 0;
    }
}

// -------- 1) GEMM: xw = x @ W  (BM=128, BK=16, 8x8/thread, f32x2 FMA) ------
//            + fused per-node attention logits
__global__ __launch_bounds__(256, 2)
void k_gemm(const float* __restrict__ x, const float* __restrict__ W,
            const float* __restrict__ att_src, const float* __restrict__ att_dst,
            int nrows) {
    __shared__ float As[16][128];   // [k][row]
    __shared__ float Bs[16][DOUT];  // [k][col]

    int tid = threadIdx.x;
    int row0 = blockIdx.x * 128;
    int ty = tid >> 4;    // 0..15 -> rows ty*8 .. ty*8+7
    int tx = tid & 15;    // 0..15 -> cols tx*8 .. tx*8+7

    unsigned long long acc2[8][4];
#pragma unroll
    for (int i = 0; i < 8; i++)
#pragma unroll
        for (int j = 0; j < 4; j++) acc2[i][j] = 0ULL;

    for (int k0 = 0; k0 < DIN; k0 += 16) {
#pragma unroll
        for (int p = 0; p < 2; p++) {
            int fi = tid + 256 * p;
            int arow = fi >> 2;
            int kq = fi & 3;
            float4 av = make_float4(0.f, 0.f, 0.f, 0.f);
            int gr = row0 + arow;
            if (gr < nrows)
                av = *reinterpret_cast<const float4*>(x + (size_t)gr * DIN + k0 + 4 * kq);
            As[4 * kq + 0][arow] = av.x;
            As[4 * kq + 1][arow] = av.y;
            As[4 * kq + 2][arow] = av.z;
            As[4 * kq + 3][arow] = av.w;
        }
#pragma unroll
        for (int p = 0; p < 2; p++) {
            int fi = tid + 256 * p;
            int bk = fi >> 5;
            int bc = (fi & 31) * 4;
            float4 bv = *reinterpret_cast<const float4*>(W + (size_t)(k0 + bk) * DOUT + bc);
            *reinterpret_cast<float4*>(&Bs[bk][bc]) = bv;
        }
        __syncthreads();

#pragma unroll
        for (int kk = 0; kk < 16; kk++) {
            ulonglong2 b01 = *reinterpret_cast<ulonglong2*>(&Bs[kk][tx * 8]);
            ulonglong2 b23 = *reinterpret_cast<ulonglong2*>(&Bs[kk][tx * 8 + 4]);
            unsigned long long bp[4] = {b01.x, b01.y, b23.x, b23.y};
            float4 a03 = *reinterpret_cast<float4*>(&As[kk][ty * 8]);
            float4 a47 = *reinterpret_cast<float4*>(&As[kk][ty * 8 + 4]);
            float a[8] = {a03.x, a03.y, a03.z, a03.w, a47.x, a47.y, a47.z, a47.w};
#pragma unroll
            for (int i = 0; i < 8; i++) {
                unsigned long long ap = pack2(a[i], a[i]);
#pragma unroll
                for (int j = 0; j < 4; j++) fma2(acc2[i][j], ap, bp[j]);
            }
        }
        __syncthreads();
    }

    float4 as0 = *reinterpret_cast<const float4*>(att_src + tx * 8);
    float4 as1 = *reinterpret_cast<const float4*>(att_src + tx * 8 + 4);
    float4 ad0 = *reinterpret_cast<const float4*>(att_dst + tx * 8);
    float4 ad1 = *reinterpret_cast<const float4*>(att_dst + tx * 8 + 4);
#pragma unroll
    for (int i = 0; i < 8; i++) {
        float c[8];
        unpack2(acc2[i][0], c[0], c[1]);
        unpack2(acc2[i][1], c[2], c[3]);
        unpack2(acc2[i][2], c[4], c[5]);
        unpack2(acc2[i][3], c[6], c[7]);
        int gr = row0 + ty * 8 + i;

        float s = c[0]*as0.x + c[1]*as0.y + c[2]*as0.z + c[3]*as0.w
                + c[4]*as1.x + c[5]*as1.y + c[6]*as1.z + c[7]*as1.w;
        float d = c[0]*ad0.x + c[1]*ad0.y + c[2]*ad0.z + c[3]*ad0.w
                + c[4]*ad1.x + c[5]*ad1.y + c[6]*ad1.z + c[7]*ad1.w;
#pragma unroll
        for (int off = 8; off > 0; off >>= 1) {
            s += __shfl_xor_sync(0xFFFFFFFFu, s, off);
            d += __shfl_xor_sync(0xFFFFFFFFu, d, off);
        }
        if (gr < nrows) {
            *reinterpret_cast<float4*>(&g_xw[(size_t)gr * DOUT + tx * 8]) =
                make_float4(c[0], c[1], c[2], c[3]);
            *reinterpret_cast<float4*>(&g_xw[(size_t)gr * DOUT + tx * 8 + 4]) =
                make_float4(c[4], c[5], c[6], c[7]);
            if (tx == 0) { g_asrc[gr] = s; g_adst[gr] = d; }
        }
    }
}

// ---------------- 2) histogram of destinations ------------------------------
__global__ void k_count(const int* __restrict__ ei, int E) {
    int i0 = (blockIdx.x * blockDim.x + threadIdx.x) * 4;
    int is64 = g_is64;
#pragma unroll
    for (int r = 0; r < 4; r++) {
        int i = i0 + r;
        if (i < E) atomicAdd(&g_cnt[edge_dst(ei, i, E, is64)], 1);
    }
}

// ---------------- 3) parallel exclusive scan (3 launches) -------------------
// scan1: per-block (1024 elems) local exclusive prefix + block total
__global__ __launch_bounds__(256)
void k_scan1(int n) {
    __shared__ int warp_sums[8];
    int blk = blockIdx.x;
    int t = threadIdx.x;
    int lane = t & 31, wid = t >> 5;
    int base = blk * 1024 + t * 4;

    int v[4];
#pragma unroll
    for (int i = 0; i < 4; i++) {
        int idx = base + i;
        v[i] = (idx < n) ? g_cnt[idx] : 0;
    }
    int local = v[0] + v[1] + v[2] + v[3];

    int inc = local;
#pragma unroll
    for (int off = 1; off < 32; off <<= 1) {
        int x = __shfl_up_sync(0xFFFFFFFFu, inc, off);
        if (lane >= off) inc += x;
    }
    if (lane == 31) warp_sums[wid] = inc;
    __syncthreads();
    if (wid == 0) {
        int ws = (lane < 8) ? warp_sums[lane] : 0;
#pragma unroll
        for (int off = 1; off < 8; off <<= 1) {
            int x = __shfl_up_sync(0xFFFFFFFFu, ws, off);
            if (lane >= off) ws += x;
        }
        if (lane < 8) warp_sums[lane] = ws;
    }
    __syncthreads();

    int run = inc - local + ((wid > 0) ? warp_sums[wid - 1] : 0);
#pragma unroll
    for (int i = 0; i < 4; i++) {
        int idx = base + i;
        if (idx < n) g_rowstart[idx] = run;
        run += v[i];
    }
    if (t == 255) g_bsum[blk] = warp_sums[7];
}

// scan2: one warp scans block totals (2 per lane, up to 64 blocks)
__global__ void k_scan2(int nb) {
    int l = threadIdx.x;   // 0..31
    int v0 = (2 * l < nb)     ? g_bsum[2 * l]     : 0;
    int v1 = (2 * l + 1 < nb) ? g_bsum[2 * l + 1] : 0;
    int local = v0 + v1;
    int inc = local;
#pragma unroll
    for (int off = 1; off < 32; off <<= 1) {
        int x = __shfl_up_sync(0xFFFFFFFFu, inc, off);
        if (l >= off) inc += x;
    }
    int excl = inc - local;
    if (2 * l < nb)     g_boff[2 * l]     = excl;
    if (2 * l + 1 < nb) g_boff[2 * l + 1] = excl + v0;
    if (l == 31) g_total = inc;
}

// scan3: add block offsets, materialize rowstart + cursor
__global__ void k_scan3(int n) {
    int i = blockIdx.x * blockDim.x + threadIdx.x;
    if (i < n) {
        int r = g_rowstart[i] + g_boff[i >> 10];
        g_rowstart[i] = r;
        g_cursor[i] = r;
    }
    if (i == 0) g_rowstart[n] = g_total;
}

// ---------------- 4) scatter edges into CSR ---------------------------------
__global__ void k_scatter(const int* __restrict__ ei, int E) {
    int i0 = (blockIdx.x * blockDim.x + threadIdx.x) * 4;
    int is64 = g_is64;
#pragma unroll
    for (int r = 0; r < 4; r++) {
        int i = i0 + r;
        if (i < E) {
            int s = edge_src(ei, i, is64);
            int d = edge_dst(ei, i, E, is64);
            int pos = atomicAdd(&g_cursor[d], 1);
            g_csr_src[pos] = s;
        }
    }
}

// ------ 5) per-node softmax + aggregation + bias + ELU (one warp/node) ------
__global__ __launch_bounds__(256)
void k_node(float* __restrict__ out, const float* __restrict__ bias, int n) {
    __shared__ int   sh_src[8][WCAP];
    __shared__ float sh_ex[8][WCAP];

    int w = threadIdx.x >> 5;
    int d = blockIdx.x * 8 + w;
    if (d >= n) return;
    int l = threadIdx.x & 31;

    int row = g_rowstart[d];
    int end = g_rowstart[d + 1];
    int deg = end - row;
    float adv = g_adst[d];

    float es = g_asrc[d] + adv;
    es = (es > 0.0f) ? es : NEG_SLOPE * es;
    float ex_self = __expf(es);
    float sum = 0.0f;
    for (int j = l; j < deg; j += 32) {
        int s = g_csr_src[row + j];
        float e = g_asrc[s] + adv;
        e = (e > 0.0f) ? e : NEG_SLOPE * e;
        float ex = __expf(e);
        sum += ex;
        if (j < WCAP) { sh_src[w][j] = s; sh_ex[w][j] = ex; }
    }
#pragma unroll
    for (int off = 16; off > 0; off >>= 1)
        sum += __shfl_xor_sync(0xFFFFFFFFu, sum, off);
    float inv = 1.0f / (sum + ex_self);
    __syncwarp();

    float4 acc;
    {
        float a = ex_self * inv;
        float4 v = *reinterpret_cast<const float4*>(&g_xw[(size_t)d * DOUT + l * 4]);
        acc.x = a * v.x; acc.y = a * v.y; acc.z = a * v.z; acc.w = a * v.w;
    }
    int m = (deg < WCAP) ? deg : WCAP;
    int j = 0;
    for (; j + 4 <= m; j += 4) {
        int s0 = sh_src[w][j + 0], s1 = sh_src[w][j + 1];
        int s2 = sh_src[w][j + 2], s3 = sh_src[w][j + 3];
        float a0 = sh_ex[w][j + 0] * inv, a1 = sh_ex[w][j + 1] * inv;
        float a2 = sh_ex[w][j + 2] * inv, a3 = sh_ex[w][j + 3] * inv;
        float4 v0 = *reinterpret_cast<const float4*>(&g_xw[(size_t)s0 * DOUT + l * 4]);
        float4 v1 = *reinterpret_cast<const float4*>(&g_xw[(size_t)s1 * DOUT + l * 4]);
        float4 v2 = *reinterpret_cast<const float4*>(&g_xw[(size_t)s2 * DOUT + l * 4]);
        float4 v3 = *reinterpret_cast<const float4*>(&g_xw[(size_t)s3 * DOUT + l * 4]);
        acc.x = fmaf(a0, v0.x, acc.x); acc.y = fmaf(a0, v0.y, acc.y);
        acc.z = fmaf(a0, v0.z, acc.z); acc.w = fmaf(a0, v0.w, acc.w);
        acc.x = fmaf(a1, v1.x, acc.x); acc.y = fmaf(a1, v1.y, acc.y);
        acc.z = fmaf(a1, v1.z, acc.z); acc.w = fmaf(a1, v1.w, acc.w);
        acc.x = fmaf(a2, v2.x, acc.x); acc.y = fmaf(a2, v2.y, acc.y);
        acc.z = fmaf(a2, v2.z, acc.z); acc.w = fmaf(a2, v2.w, acc.w);
        acc.x = fmaf(a3, v3.x, acc.x); acc.y = fmaf(a3, v3.y, acc.y);
        acc.z = fmaf(a3, v3.z, acc.z); acc.w = fmaf(a3, v3.w, acc.w);
    }
    for (; j < m; j++) {
        int s = sh_src[w][j];
        float a = sh_ex[w][j] * inv;
        float4 v = *reinterpret_cast<const float4*>(&g_xw[(size_t)s * DOUT + l * 4]);
        acc.x = fmaf(a, v.x, acc.x); acc.y = fmaf(a, v.y, acc.y);
        acc.z = fmaf(a, v.z, acc.z); acc.w = fmaf(a, v.w, acc.w);
    }
    for (int jj = WCAP; jj < deg; jj++) {
        int s = g_csr_src[row + jj];
        float e = g_asrc[s] + adv;
        e = (e > 0.0f) ? e : NEG_SLOPE * e;
        float a = __expf(e) * inv;
        float4 v = *reinterpret_cast<const float4*>(&g_xw[(size_t)s * DOUT + l * 4]);
        acc.x = fmaf(a, v.x, acc.x); acc.y = fmaf(a, v.y, acc.y);
        acc.z = fmaf(a, v.z, acc.z); acc.w = fmaf(a, v.w, acc.w);
    }

    float4 b = *reinterpret_cast<const float4*>(bias + l * 4);
    acc.x += b.x; acc.y += b.y; acc.z += b.z; acc.w += b.w;
    acc.x = (acc.x > 0.0f) ? acc.x : expm1f(acc.x);
    acc.y = (acc.y > 0.0f) ? acc.y : expm1f(acc.y);
    acc.z = (acc.z > 0.0f) ? acc.z : expm1f(acc.z);
    acc.w = (acc.w > 0.0f) ? acc.w : expm1f(acc.w);
    *reinterpret_cast<float4*>(&out[(size_t)d * DOUT + l * 4]) = acc;
}

// ---------------- launch ---------------------------------------------------
extern "C" void kernel_launch(void* const* d_in, const int* in_sizes, int n_in,
                              void* d_out, int out_size) {
    const float* x    = (const float*)d_in[0];
    const int*   ei   = (const int*)d_in[1];    // int32 words (int64 auto-detected)
    const float* W    = (const float*)d_in[2];
    const float* asv  = (const float*)d_in[3];
    const float* adv  = (const float*)d_in[4];
    const float* bias = (const float*)d_in[5];
    float* out = (float*)d_out;

    int n = in_sizes[0] / DIN;      // 50000
    int E = in_sizes[1] / 2;        // 800000
    int nb = (n + 1023) / 1024;     // scan blocks (49)

    int t = 256;
    k_detect_zero<<<(n + t - 1) / t, t>>>(ei, n);
    k_gemm<<<(n + 127) / 128, 256>>>(x, W, asv, adv, n);
    k_count<<<(E + 4 * t - 1) / (4 * t), t>>>(ei, E);
    k_scan1<<<nb, 256>>>(n);
    k_scan2<<<1, 32>>>(nb);
    k_scan3<<<(n + t - 1) / t, t>>>(n);
    k_scatter<<<(E + 4 * t - 1) / (4 * t), t>>>(ei, E);
    k_node<<<(n + 7) / 8, t>>>(out, bias, n);
}

// round 14
// speedup vs baseline: 3.0946x; 1.0714x over previous
#include <cuda_runtime.h>
#include <cuda_fp16.h>

// Problem constants (fixed by the dataset)
#define NMAX 50000
#define EMAX 800000
#define DOUT 128
#define DIN 128
#define NEG_SLOPE 0.2f
#define WCAP 128   // per-warp staged edges in k_node

// ---------------- scratch (device globals; no allocation allowed) ----------
__device__ __half g_xwh[NMAX * DOUT];     // 12.8 MB, fp16 xw (k_node gather)
__device__ float  g_asrc[NMAX];
__device__ float  g_adst[NMAX];
__device__ int    g_cnt[NMAX];            // per-dst edge count (self-cleaning)
__device__ int    g_rowstart[NMAX + 1];   // CSR row offsets
__device__ int    g_cursor[NMAX];         // scatter cursors
__device__ int    g_csr_src[EMAX];        // CSR: src per edge, grouped by dst
__device__ int    g_is64;                 // edge_index stored as int64?
__device__ int    g_bsum[64];             // scan: per-block totals
__device__ int    g_boff[64];             // scan: per-block exclusive offsets
__device__ int    g_total;                // scan: grand total

// ---------------- packed f32x2 helpers --------------------------------------
__device__ __forceinline__ unsigned long long pack2(float x, float y) {
    unsigned long long r;
    asm("mov.b64 %0, {%1, %2};" : "=l"(r) : "f"(x), "f"(y));
    return r;
}
__device__ __forceinline__ void unpack2(unsigned long long v, float& x, float& y) {
    asm("mov.b64 {%0, %1}, %2;" : "=f"(x), "=f"(y) : "l"(v));
}
__device__ __forceinline__ void fma2(unsigned long long& d,
                                     unsigned long long a, unsigned long long b) {
    asm("fma.rn.f32x2 %0, %1, %2, %0;" : "+l"(d) : "l"(a), "l"(b));
}

// ---------------- 0) detect edge-index dtype (int32 vs int64) --------------
__global__ void k_detect(const int* __restrict__ w) {
    if (threadIdx.x == 0) {
        int odd_or = 0;
#pragma unroll
        for (int j = 0; j < 64; j++) odd_or |= w[2 * j + 1];
        g_is64 = (odd_or == 0) ? 1 : 0;
    }
}

// -------- 1) GEMM: xw = x @ W  (BM=128, BK=16, 8x8/thread, f32x2 FMA) ------
//            + fused attention logits; stores xw as fp16
__global__ __launch_bounds__(256, 2)
void k_gemm(const float* __restrict__ x, const float* __restrict__ W,
            const float* __restrict__ att_src, const float* __restrict__ att_dst,
            int nrows) {
    __shared__ float As[16][128];   // [k][row]
    __shared__ float Bs[16][DOUT];  // [k][col]

    int tid = threadIdx.x;
    int row0 = blockIdx.x * 128;
    int ty = tid >> 4;    // 0..15 -> rows ty*8 .. ty*8+7
    int tx = tid & 15;    // 0..15 -> cols tx*8 .. tx*8+7

    unsigned long long acc2[8][4];
#pragma unroll
    for (int i = 0; i < 8; i++)
#pragma unroll
        for (int j = 0; j < 4; j++) acc2[i][j] = 0ULL;

    for (int k0 = 0; k0 < DIN; k0 += 16) {
#pragma unroll
        for (int p = 0; p < 2; p++) {
            int fi = tid + 256 * p;
            int arow = fi >> 2;
            int kq = fi & 3;
            float4 av = make_float4(0.f, 0.f, 0.f, 0.f);
            int gr = row0 + arow;
            if (gr < nrows)
                av = *reinterpret_cast<const float4*>(x + (size_t)gr * DIN + k0 + 4 * kq);
            As[4 * kq + 0][arow] = av.x;
            As[4 * kq + 1][arow] = av.y;
            As[4 * kq + 2][arow] = av.z;
            As[4 * kq + 3][arow] = av.w;
        }
#pragma unroll
        for (int p = 0; p < 2; p++) {
            int fi = tid + 256 * p;
            int bk = fi >> 5;
            int bc = (fi & 31) * 4;
            float4 bv = *reinterpret_cast<const float4*>(W + (size_t)(k0 + bk) * DOUT + bc);
            *reinterpret_cast<float4*>(&Bs[bk][bc]) = bv;
        }
        __syncthreads();

#pragma unroll
        for (int kk = 0; kk < 16; kk++) {
            ulonglong2 b01 = *reinterpret_cast<ulonglong2*>(&Bs[kk][tx * 8]);
            ulonglong2 b23 = *reinterpret_cast<ulonglong2*>(&Bs[kk][tx * 8 + 4]);
            unsigned long long bp[4] = {b01.x, b01.y, b23.x, b23.y};
            float4 a03 = *reinterpret_cast<float4*>(&As[kk][ty * 8]);
            float4 a47 = *reinterpret_cast<float4*>(&As[kk][ty * 8 + 4]);
            float a[8] = {a03.x, a03.y, a03.z, a03.w, a47.x, a47.y, a47.z, a47.w};
#pragma unroll
            for (int i = 0; i < 8; i++) {
                unsigned long long ap = pack2(a[i], a[i]);
#pragma unroll
                for (int j = 0; j < 4; j++) fma2(acc2[i][j], ap, bp[j]);
            }
        }
        __syncthreads();
    }

    float4 as0 = *reinterpret_cast<const float4*>(att_src + tx * 8);
    float4 as1 = *reinterpret_cast<const float4*>(att_src + tx * 8 + 4);
    float4 ad0 = *reinterpret_cast<const float4*>(att_dst + tx * 8);
    float4 ad1 = *reinterpret_cast<const float4*>(att_dst + tx * 8 + 4);
#pragma unroll
    for (int i = 0; i < 8; i++) {
        float c[8];
        unpack2(acc2[i][0], c[0], c[1]);
        unpack2(acc2[i][1], c[2], c[3]);
        unpack2(acc2[i][2], c[4], c[5]);
        unpack2(acc2[i][3], c[6], c[7]);
        int gr = row0 + ty * 8 + i;

        float s = c[0]*as0.x + c[1]*as0.y + c[2]*as0.z + c[3]*as0.w
                + c[4]*as1.x + c[5]*as1.y + c[6]*as1.z + c[7]*as1.w;
        float d = c[0]*ad0.x + c[1]*ad0.y + c[2]*ad0.z + c[3]*ad0.w
                + c[4]*ad1.x + c[5]*ad1.y + c[6]*ad1.z + c[7]*ad1.w;
#pragma unroll
        for (int off = 8; off > 0; off >>= 1) {
            s += __shfl_xor_sync(0xFFFFFFFFu, s, off);
            d += __shfl_xor_sync(0xFFFFFFFFu, d, off);
        }
        if (gr < nrows) {
            __half2 hh[4];
            hh[0] = __float22half2_rn(make_float2(c[0], c[1]));
            hh[1] = __float22half2_rn(make_float2(c[2], c[3]));
            hh[2] = __float22half2_rn(make_float2(c[4], c[5]));
            hh[3] = __float22half2_rn(make_float2(c[6], c[7]));
            *reinterpret_cast<uint4*>(&g_xwh[(size_t)gr * DOUT + tx * 8]) =
                *reinterpret_cast<uint4*>(hh);
            if (tx == 0) { g_asrc[gr] = s; g_adst[gr] = d; }
        }
    }
}

// ---------------- 2) histogram of destinations (vectorized loads) ----------
__global__ void k_count(const int* __restrict__ ei, int E) {
    int i0 = (blockIdx.x * blockDim.x + threadIdx.x) * 4;
    if (i0 >= E) return;
    int is64 = g_is64;
    if (i0 + 4 <= E) {
        int d0, d1, d2, d3;
        if (is64) {
            int4 a = *reinterpret_cast<const int4*>(&ei[2 * ((size_t)E + i0)]);
            int4 b = *reinterpret_cast<const int4*>(&ei[2 * ((size_t)E + i0) + 4]);
            d0 = a.x; d1 = a.z; d2 = b.x; d3 = b.z;
        } else {
            int4 a = *reinterpret_cast<const int4*>(&ei[E + i0]);
            d0 = a.x; d1 = a.y; d2 = a.z; d3 = a.w;
        }
        atomicAdd(&g_cnt[d0], 1);
        atomicAdd(&g_cnt[d1], 1);
        atomicAdd(&g_cnt[d2], 1);
        atomicAdd(&g_cnt[d3], 1);
    } else {
        for (int i = i0; i < E; i++) {
            int d = is64 ? ei[2 * ((size_t)E + i)] : ei[E + i];
            atomicAdd(&g_cnt[d], 1);
        }
    }
}

// ---------------- 3) parallel exclusive scan (3 launches) -------------------
__global__ __launch_bounds__(256)
void k_scan1(int n) {
    __shared__ int warp_sums[8];
    int blk = blockIdx.x;
    int t = threadIdx.x;
    int lane = t & 31, wid = t >> 5;
    int base = blk * 1024 + t * 4;

    int v[4];
#pragma unroll
    for (int i = 0; i < 4; i++) {
        int idx = base + i;
        if (idx < n) { v[i] = g_cnt[idx]; g_cnt[idx] = 0; }  // self-cleaning
        else v[i] = 0;
    }
    int local = v[0] + v[1] + v[2] + v[3];

    int inc = local;
#pragma unroll
    for (int off = 1; off < 32; off <<= 1) {
        int x = __shfl_up_sync(0xFFFFFFFFu, inc, off);
        if (lane >= off) inc += x;
    }
    if (lane == 31) warp_sums[wid] = inc;
    __syncthreads();
    if (wid == 0) {
        int ws = (lane < 8) ? warp_sums[lane] : 0;
#pragma unroll
        for (int off = 1; off < 8; off <<= 1) {
            int x = __shfl_up_sync(0xFFFFFFFFu, ws, off);
            if (lane >= off) ws += x;
        }
        if (lane < 8) warp_sums[lane] = ws;
    }
    __syncthreads();

    int run = inc - local + ((wid > 0) ? warp_sums[wid - 1] : 0);
#pragma unroll
    for (int i = 0; i < 4; i++) {
        int idx = base + i;
        if (idx < n) g_rowstart[idx] = run;
        run += v[i];
    }
    if (t == 255) g_bsum[blk] = warp_sums[7];
}

__global__ void k_scan2(int nb) {
    int l = threadIdx.x;   // 0..31
    int v0 = (2 * l < nb)     ? g_bsum[2 * l]     : 0;
    int v1 = (2 * l + 1 < nb) ? g_bsum[2 * l + 1] : 0;
    int local = v0 + v1;
    int inc = local;
#pragma unroll
    for (int off = 1; off < 32; off <<= 1) {
        int x = __shfl_up_sync(0xFFFFFFFFu, inc, off);
        if (l >= off) inc += x;
    }
    int excl = inc - local;
    if (2 * l < nb)     g_boff[2 * l]     = excl;
    if (2 * l + 1 < nb) g_boff[2 * l + 1] = excl + v0;
    if (l == 31) g_total = inc;
}

__global__ void k_scan3(int n) {
    int i = blockIdx.x * blockDim.x + threadIdx.x;
    if (i < n) {
        int r = g_rowstart[i] + g_boff[i >> 10];
        g_rowstart[i] = r;
        g_cursor[i] = r;
    }
    if (i == 0) g_rowstart[n] = g_total;
}

// ---------------- 4) scatter edges into CSR (vectorized loads) --------------
__global__ void k_scatter(const int* __restrict__ ei, int E) {
    int i0 = (blockIdx.x * blockDim.x + threadIdx.x) * 4;
    if (i0 >= E) return;
    int is64 = g_is64;
    if (i0 + 4 <= E) {
        int s0, s1, s2, s3, d0, d1, d2, d3;
        if (is64) {
            int4 sa = *reinterpret_cast<const int4*>(&ei[2 * (size_t)i0]);
            int4 sb = *reinterpret_cast<const int4*>(&ei[2 * (size_t)i0 + 4]);
            int4 da = *reinterpret_cast<const int4*>(&ei[2 * ((size_t)E + i0)]);
            int4 db = *reinterpret_cast<const int4*>(&ei[2 * ((size_t)E + i0) + 4]);
            s0 = sa.x; s1 = sa.z; s2 = sb.x; s3 = sb.z;
            d0 = da.x; d1 = da.z; d2 = db.x; d3 = db.z;
        } else {
            int4 sa = *reinterpret_cast<const int4*>(&ei[i0]);
            int4 da = *reinterpret_cast<const int4*>(&ei[E + i0]);
            s0 = sa.x; s1 = sa.y; s2 = sa.z; s3 = sa.w;
            d0 = da.x; d1 = da.y; d2 = da.z; d3 = da.w;
        }
        g_csr_src[atomicAdd(&g_cursor[d0], 1)] = s0;
        g_csr_src[atomicAdd(&g_cursor[d1], 1)] = s1;
        g_csr_src[atomicAdd(&g_cursor[d2], 1)] = s2;
        g_csr_src[atomicAdd(&g_cursor[d3], 1)] = s3;
    } else {
        for (int i = i0; i < E; i++) {
            int s = is64 ? ei[2 * (size_t)i] : ei[i];
            int d = is64 ? ei[2 * ((size_t)E + i)] : ei[E + i];
            g_csr_src[atomicAdd(&g_cursor[d], 1)] = s;
        }
    }
}

// ------ 5) per-node softmax + aggregation + bias + ELU (one warp/node) ------
__device__ __forceinline__ float4 load_xwh(int node, int l) {
    uint2 u = *reinterpret_cast<const uint2*>(&g_xwh[(size_t)node * DOUT + l * 4]);
    float2 f0 = __half22float2(*reinterpret_cast<__half2*>(&u.x));
    float2 f1 = __half22float2(*reinterpret_cast<__half2*>(&u.y));
    return make_float4(f0.x, f0.y, f1.x, f1.y);
}

__global__ __launch_bounds__(256)
void k_node(float* __restrict__ out, const float* __restrict__ bias, int n) {
    __shared__ int   sh_src[8][WCAP];
    __shared__ float sh_ex[8][WCAP];

    int w = threadIdx.x >> 5;
    int d = blockIdx.x * 8 + w;
    if (d >= n) return;
    int l = threadIdx.x & 31;

    int row = g_rowstart[d];
    int end = g_rowstart[d + 1];
    int deg = end - row;
    float adv = g_adst[d];

    float es = g_asrc[d] + adv;
    es = (es > 0.0f) ? es : NEG_SLOPE * es;
    float ex_self = __expf(es);
    float sum = 0.0f;
    for (int j = l; j < deg; j += 32) {
        int s = g_csr_src[row + j];
        float e = g_asrc[s] + adv;
        e = (e > 0.0f) ? e : NEG_SLOPE * e;
        float ex = __expf(e);
        sum += ex;
        if (j < WCAP) { sh_src[w][j] = s; sh_ex[w][j] = ex; }
    }
#pragma unroll
    for (int off = 16; off > 0; off >>= 1)
        sum += __shfl_xor_sync(0xFFFFFFFFu, sum, off);
    float inv = 1.0f / (sum + ex_self);
    __syncwarp();

    float4 acc;
    {
        float a = ex_self * inv;
        float4 v = load_xwh(d, l);
        acc.x = a * v.x; acc.y = a * v.y; acc.z = a * v.z; acc.w = a * v.w;
    }
    int m = (deg < WCAP) ? deg : WCAP;
    int j = 0;
    for (; j + 4 <= m; j += 4) {
        int s0 = sh_src[w][j + 0], s1 = sh_src[w][j + 1];
        int s2 = sh_src[w][j + 2], s3 = sh_src[w][j + 3];
        float a0 = sh_ex[w][j + 0] * inv, a1 = sh_ex[w][j + 1] * inv;
        float a2 = sh_ex[w][j + 2] * inv, a3 = sh_ex[w][j + 3] * inv;
        float4 v0 = load_xwh(s0, l);
        float4 v1 = load_xwh(s1, l);
        float4 v2 = load_xwh(s2, l);
        float4 v3 = load_xwh(s3, l);
        acc.x = fmaf(a0, v0.x, acc.x); acc.y = fmaf(a0, v0.y, acc.y);
        acc.z = fmaf(a0, v0.z, acc.z); acc.w = fmaf(a0, v0.w, acc.w);
        acc.x = fmaf(a1, v1.x, acc.x); acc.y = fmaf(a1, v1.y, acc.y);
        acc.z = fmaf(a1, v1.z, acc.z); acc.w = fmaf(a1, v1.w, acc.w);
        acc.x = fmaf(a2, v2.x, acc.x); acc.y = fmaf(a2, v2.y, acc.y);
        acc.z = fmaf(a2, v2.z, acc.z); acc.w = fmaf(a2, v2.w, acc.w);
        acc.x = fmaf(a3, v3.x, acc.x); acc.y = fmaf(a3, v3.y, acc.y);
        acc.z = fmaf(a3, v3.z, acc.z); acc.w = fmaf(a3, v3.w, acc.w);
    }
    for (; j < m; j++) {
        int s = sh_src[w][j];
        float a = sh_ex[w][j] * inv;
        float4 v = load_xwh(s, l);
        acc.x = fmaf(a, v.x, acc.x); acc.y = fmaf(a, v.y, acc.y);
        acc.z = fmaf(a, v.z, acc.z); acc.w = fmaf(a, v.w, acc.w);
    }
    for (int jj = WCAP; jj < deg; jj++) {
        int s = g_csr_src[row + jj];
        float e = g_asrc[s] + adv;
        e = (e > 0.0f) ? e : NEG_SLOPE * e;
        float a = __expf(e) * inv;
        float4 v = load_xwh(s, l);
        acc.x = fmaf(a, v.x, acc.x); acc.y = fmaf(a, v.y, acc.y);
        acc.z = fmaf(a, v.z, acc.z); acc.w = fmaf(a, v.w, acc.w);
    }

    float4 b = *reinterpret_cast<const float4*>(bias + l * 4);
    acc.x += b.x; acc.y += b.y; acc.z += b.z; acc.w += b.w;
    acc.x = (acc.x > 0.0f) ? acc.x : expm1f(acc.x);
    acc.y = (acc.y > 0.0f) ? acc.y : expm1f(acc.y);
    acc.z = (acc.z > 0.0f) ? acc.z : expm1f(acc.z);
    acc.w = (acc.w > 0.0f) ? acc.w : expm1f(acc.w);
    *reinterpret_cast<float4*>(&out[(size_t)d * DOUT + l * 4]) = acc;
}

// ---------------- launch ---------------------------------------------------
extern "C" void kernel_launch(void* const* d_in, const int* in_sizes, int n_in,
                              void* d_out, int out_size) {
    const float* x    = (const float*)d_in[0];
    const int*   ei   = (const int*)d_in[1];    // int32 words (int64 auto-detected)
    const float* W    = (const float*)d_in[2];
    const float* asv  = (const float*)d_in[3];
    const float* adv  = (const float*)d_in[4];
    const float* bias = (const float*)d_in[5];
    float* out = (float*)d_out;

    int n = in_sizes[0] / DIN;      // 50000
    int E = in_sizes[1] / 2;        // 800000
    int nb = (n + 1023) / 1024;     // scan blocks (49)

    int t = 256;
    k_detect<<<1, 32>>>(ei);
    k_gemm<<<(n + 127) / 128, 256>>>(x, W, asv, adv, n);
    k_count<<<(E + 4 * t - 1) / (4 * t), t>>>(ei, E);
    k_scan1<<<nb, 256>>>(n);
    k_scan2<<<1, 32>>>(nb);
    k_scan3<<<(n + t - 1) / t, t>>>(n);
    k_scatter<<<(E + 4 * t - 1) / (4 * t), t>>>(ei, E);
    k_node<<<(n + 7) / 8, t>>>(out, bias, n);
}

// round 16
// speedup vs baseline: 3.3495x; 1.0824x over previous
#include <cuda_runtime.h>
#include <cuda_fp16.h>
#include <mma.h>

using namespace nvcuda;

// Problem constants (fixed by the dataset)
#define NMAX 50000
#define EMAX 800000
#define DOUT 128
#define DIN 128
#define NEG_SLOPE 0.2f
#define WCAP 128   // per-warp staged edges in k_node

// ---------------- scratch (device globals; no allocation allowed) ----------
__device__ __half g_xwh[NMAX * DOUT];     // 12.8 MB, fp16 xw (k_node gather)
__device__ float  g_asrc[NMAX];
__device__ float  g_adst[NMAX];
__device__ int    g_cnt[NMAX];            // per-dst edge count (self-cleaning)
__device__ int    g_rowstart[NMAX + 1];   // CSR row offsets
__device__ int    g_cursor[NMAX];         // scatter cursors
__device__ int    g_csr_src[EMAX];        // CSR: src per edge, grouped by dst
__device__ int    g_is64;                 // edge_index stored as int64?
__device__ int    g_bsum[64];             // scan: per-block totals
__device__ int    g_boff[64];             // scan: per-block exclusive offsets
__device__ int    g_total;                // scan: grand total

// ---------------- 0) detect edge-index dtype (int32 vs int64) --------------
__global__ void k_detect(const int* __restrict__ w) {
    if (threadIdx.x == 0) {
        int odd_or = 0;
#pragma unroll
        for (int j = 0; j < 64; j++) odd_or |= w[2 * j + 1];
        g_is64 = (odd_or == 0) ? 1 : 0;
    }
}

// -------- 1) GEMM: xw = x @ W  (tf32 tensor cores, BM=128 x N=128) ---------
//            + fused attention logits; stores xw as fp16
__global__ __launch_bounds__(256)
void k_gemm(const float* __restrict__ x, const float* __restrict__ W,
            const float* __restrict__ att_src, const float* __restrict__ att_dst,
            int nrows) {
    __shared__ float As[128][36];      // x tile  [m][k], BK=32 (+pad)
    __shared__ float Ws[32][132];      // W tile  [k][n]      (+pad)
    __shared__ float stg[8][16][20];   // per-warp 16x16 frag staging (ld=20)
    __shared__ float s_src[128], s_dst[128];
    __shared__ float sas[128], sad[128];

    int tid = threadIdx.x;
    int lane = tid & 31;
    int wid = tid >> 5;
    int wm = wid >> 2;     // 0..1 -> rows wm*64
    int wn = wid & 3;      // 0..3 -> cols wn*32
    int row0 = blockIdx.x * 128;

    if (tid < 128) {
        s_src[tid] = 0.0f; s_dst[tid] = 0.0f;
        sas[tid] = att_src[tid]; sad[tid] = att_dst[tid];
    }

    wmma::fragment<wmma::accumulator, 16, 16, 8, float> acc[4][2];
#pragma unroll
    for (int mt = 0; mt < 4; mt++)
#pragma unroll
        for (int nt = 0; nt < 2; nt++) wmma::fill_fragment(acc[mt][nt], 0.0f);

    for (int k0 = 0; k0 < DIN; k0 += 32) {
        // stage x tile: 128 rows x 32 k  (1024 float4, 4/thread)
#pragma unroll
        for (int p = 0; p < 4; p++) {
            int fi = tid + 256 * p;
            int r = fi >> 3;            // 0..127
            int q = fi & 7;             // float4 along k
            float4 v = make_float4(0.f, 0.f, 0.f, 0.f);
            int gr = row0 + r;
            if (gr < nrows)
                v = *reinterpret_cast<const float4*>(x + (size_t)gr * DIN + k0 + 4 * q);
            As[r][4 * q + 0] = v.x; As[r][4 * q + 1] = v.y;
            As[r][4 * q + 2] = v.z; As[r][4 * q + 3] = v.w;
        }
        // stage W tile: 32 k x 128 n
#pragma unroll
        for (int p = 0; p < 4; p++) {
            int fi = tid + 256 * p;
            int kr = fi >> 5;           // 0..31
            int q = (fi & 31) * 4;
            float4 v = *reinterpret_cast<const float4*>(W + (size_t)(k0 + kr) * DOUT + q);
            Ws[kr][q + 0] = v.x; Ws[kr][q + 1] = v.y;
            Ws[kr][q + 2] = v.z; Ws[kr][q + 3] = v.w;
        }
        __syncthreads();

#pragma unroll
        for (int kk = 0; kk < 32; kk += 8) {
            wmma::fragment<wmma::matrix_a, 16, 16, 8, wmma::precision::tf32, wmma::row_major> af[4];
            wmma::fragment<wmma::matrix_b, 16, 16, 8, wmma::precision::tf32, wmma::row_major> bf[2];
#pragma unroll
            for (int mt = 0; mt < 4; mt++) {
                wmma::load_matrix_sync(af[mt], &As[wm * 64 + mt * 16][kk], 36);
#pragma unroll
                for (int i = 0; i < af[mt].num_elements; i++)
                    af[mt].x[i] = wmma::__float_to_tf32(af[mt].x[i]);
            }
#pragma unroll
            for (int nt = 0; nt < 2; nt++) {
                wmma::load_matrix_sync(bf[nt], &Ws[kk][wn * 32 + nt * 16], 132);
#pragma unroll
                for (int i = 0; i < bf[nt].num_elements; i++)
                    bf[nt].x[i] = wmma::__float_to_tf32(bf[nt].x[i]);
            }
#pragma unroll
            for (int mt = 0; mt < 4; mt++)
#pragma unroll
                for (int nt = 0; nt < 2; nt++)
                    wmma::mma_sync(acc[mt][nt], af[mt], bf[nt], acc[mt][nt]);
        }
        __syncthreads();
    }

    // epilogue: per 16x16 tile -> smem -> fp16 store + logit partials
    int r = lane >> 1;         // 0..15 row within tile
    int h = lane & 1;          // 0/1 column half (8 cols)
#pragma unroll
    for (int mt = 0; mt < 4; mt++) {
#pragma unroll
        for (int nt = 0; nt < 2; nt++) {
            __syncwarp();
            wmma::store_matrix_sync(&stg[wid][0][0], acc[mt][nt], 20, wmma::mem_row_major);
            __syncwarp();
            int br = wm * 64 + mt * 16 + r;       // row within block
            int gr = row0 + br;
            int c0 = wn * 32 + nt * 16 + h * 8;   // global col
            float4 v0 = *reinterpret_cast<float4*>(&stg[wid][r][h * 8]);
            float4 v1 = *reinterpret_cast<float4*>(&stg[wid][r][h * 8 + 4]);
            // logit partials over these 8 cols
            float ps = v0.x * sas[c0]     + v0.y * sas[c0 + 1] + v0.z * sas[c0 + 2] + v0.w * sas[c0 + 3]
                     + v1.x * sas[c0 + 4] + v1.y * sas[c0 + 5] + v1.z * sas[c0 + 6] + v1.w * sas[c0 + 7];
            float pd = v0.x * sad[c0]     + v0.y * sad[c0 + 1] + v0.z * sad[c0 + 2] + v0.w * sad[c0 + 3]
                     + v1.x * sad[c0 + 4] + v1.y * sad[c0 + 5] + v1.z * sad[c0 + 6] + v1.w * sad[c0 + 7];
            atomicAdd(&s_src[br], ps);
            atomicAdd(&s_dst[br], pd);
            if (gr < nrows) {
                __half2 hh[4];
                hh[0] = __float22half2_rn(make_float2(v0.x, v0.y));
                hh[1] = __float22half2_rn(make_float2(v0.z, v0.w));
                hh[2] = __float22half2_rn(make_float2(v1.x, v1.y));
                hh[3] = __float22half2_rn(make_float2(v1.z, v1.w));
                *reinterpret_cast<uint4*>(&g_xwh[(size_t)gr * DOUT + c0]) =
                    *reinterpret_cast<uint4*>(hh);
            }
        }
    }
    __syncthreads();
    if (tid < 128) {
        int gr = row0 + tid;
        if (gr < nrows) { g_asrc[gr] = s_src[tid]; g_adst[gr] = s_dst[tid]; }
    }
}

// ---------------- 2) histogram of destinations (vectorized loads) ----------
__global__ void k_count(const int* __restrict__ ei, int E) {
    int i0 = (blockIdx.x * blockDim.x + threadIdx.x) * 4;
    if (i0 >= E) return;
    int is64 = g_is64;
    if (i0 + 4 <= E) {
        int d0, d1, d2, d3;
        if (is64) {
            int4 a = *reinterpret_cast<const int4*>(&ei[2 * ((size_t)E + i0)]);
            int4 b = *reinterpret_cast<const int4*>(&ei[2 * ((size_t)E + i0) + 4]);
            d0 = a.x; d1 = a.z; d2 = b.x; d3 = b.z;
        } else {
            int4 a = *reinterpret_cast<const int4*>(&ei[E + i0]);
            d0 = a.x; d1 = a.y; d2 = a.z; d3 = a.w;
        }
        atomicAdd(&g_cnt[d0], 1);
        atomicAdd(&g_cnt[d1], 1);
        atomicAdd(&g_cnt[d2], 1);
        atomicAdd(&g_cnt[d3], 1);
    } else {
        for (int i = i0; i < E; i++) {
            int d = is64 ? ei[2 * ((size_t)E + i)] : ei[E + i];
            atomicAdd(&g_cnt[d], 1);
        }
    }
}

// ---------------- 3) parallel exclusive scan (3 launches) -------------------
__global__ __launch_bounds__(256)
void k_scan1(int n) {
    __shared__ int warp_sums[8];
    int blk = blockIdx.x;
    int t = threadIdx.x;
    int lane = t & 31, wid = t >> 5;
    int base = blk * 1024 + t * 4;

    int v[4];
#pragma unroll
    for (int i = 0; i < 4; i++) {
        int idx = base + i;
        if (idx < n) { v[i] = g_cnt[idx]; g_cnt[idx] = 0; }  // self-cleaning
        else v[i] = 0;
    }
    int local = v[0] + v[1] + v[2] + v[3];

    int inc = local;
#pragma unroll
    for (int off = 1; off < 32; off <<= 1) {
        int x = __shfl_up_sync(0xFFFFFFFFu, inc, off);
        if (lane >= off) inc += x;
    }
    if (lane == 31) warp_sums[wid] = inc;
    __syncthreads();
    if (wid == 0) {
        int ws = (lane < 8) ? warp_sums[lane] : 0;
#pragma unroll
        for (int off = 1; off < 8; off <<= 1) {
            int x = __shfl_up_sync(0xFFFFFFFFu, ws, off);
            if (lane >= off) ws += x;
        }
        if (lane < 8) warp_sums[lane] = ws;
    }
    __syncthreads();

    int run = inc - local + ((wid > 0) ? warp_sums[wid - 1] : 0);
#pragma unroll
    for (int i = 0; i < 4; i++) {
        int idx = base + i;
        if (idx < n) g_rowstart[idx] = run;
        run += v[i];
    }
    if (t == 255) g_bsum[blk] = warp_sums[7];
}

__global__ void k_scan2(int nb) {
    int l = threadIdx.x;   // 0..31
    int v0 = (2 * l < nb)     ? g_bsum[2 * l]     : 0;
    int v1 = (2 * l + 1 < nb) ? g_bsum[2 * l + 1] : 0;
    int local = v0 + v1;
    int inc = local;
#pragma unroll
    for (int off = 1; off < 32; off <<= 1) {
        int x = __shfl_up_sync(0xFFFFFFFFu, inc, off);
        if (l >= off) inc += x;
    }
    int excl = inc - local;
    if (2 * l < nb)     g_boff[2 * l]     = excl;
    if (2 * l + 1 < nb) g_boff[2 * l + 1] = excl + v0;
    if (l == 31) g_total = inc;
}

__global__ void k_scan3(int n) {
    int i = blockIdx.x * blockDim.x + threadIdx.x;
    if (i < n) {
        int r = g_rowstart[i] + g_boff[i >> 10];
        g_rowstart[i] = r;
        g_cursor[i] = r;
    }
    if (i == 0) g_rowstart[n] = g_total;
}

// ---------------- 4) scatter edges into CSR (vectorized loads) --------------
__global__ void k_scatter(const int* __restrict__ ei, int E) {
    int i0 = (blockIdx.x * blockDim.x + threadIdx.x) * 4;
    if (i0 >= E) return;
    int is64 = g_is64;
    if (i0 + 4 <= E) {
        int s0, s1, s2, s3, d0, d1, d2, d3;
        if (is64) {
            int4 sa = *reinterpret_cast<const int4*>(&ei[2 * (size_t)i0]);
            int4 sb = *reinterpret_cast<const int4*>(&ei[2 * (size_t)i0 + 4]);
            int4 da = *reinterpret_cast<const int4*>(&ei[2 * ((size_t)E + i0)]);
            int4 db = *reinterpret_cast<const int4*>(&ei[2 * ((size_t)E + i0) + 4]);
            s0 = sa.x; s1 = sa.z; s2 = sb.x; s3 = sb.z;
            d0 = da.x; d1 = da.z; d2 = db.x; d3 = db.z;
        } else {
            int4 sa = *reinterpret_cast<const int4*>(&ei[i0]);
            int4 da = *reinterpret_cast<const int4*>(&ei[E + i0]);
            s0 = sa.x; s1 = sa.y; s2 = sa.z; s3 = sa.w;
            d0 = da.x; d1 = da.y; d2 = da.z; d3 = da.w;
        }
        g_csr_src[atomicAdd(&g_cursor[d0], 1)] = s0;
        g_csr_src[atomicAdd(&g_cursor[d1], 1)] = s1;
        g_csr_src[atomicAdd(&g_cursor[d2], 1)] = s2;
        g_csr_src[atomicAdd(&g_cursor[d3], 1)] = s3;
    } else {
        for (int i = i0; i < E; i++) {
            int s = is64 ? ei[2 * (size_t)i] : ei[i];
            int d = is64 ? ei[2 * ((size_t)E + i)] : ei[E + i];
            g_csr_src[atomicAdd(&g_cursor[d], 1)] = s;
        }
    }
}

// ------ 5) per-node softmax + aggregation + bias + ELU (one warp/node) ------
__device__ __forceinline__ float4 load_xwh(int node, int l) {
    uint2 u = *reinterpret_cast<const uint2*>(&g_xwh[(size_t)node * DOUT + l * 4]);
    float2 f0 = __half22float2(*reinterpret_cast<__half2*>(&u.x));
    float2 f1 = __half22float2(*reinterpret_cast<__half2*>(&u.y));
    return make_float4(f0.x, f0.y, f1.x, f1.y);
}

__global__ __launch_bounds__(256)
void k_node(float* __restrict__ out, const float* __restrict__ bias, int n) {
    __shared__ int   sh_src[8][WCAP];
    __shared__ float sh_ex[8][WCAP];

    int w = threadIdx.x >> 5;
    int d = blockIdx.x * 8 + w;
    if (d >= n) return;
    int l = threadIdx.x & 31;

    int row = g_rowstart[d];
    int end = g_rowstart[d + 1];
    int deg = end - row;
    float adv = g_adst[d];

    float es = g_asrc[d] + adv;
    es = (es > 0.0f) ? es : NEG_SLOPE * es;
    float ex_self = __expf(es);
    float sum = 0.0f;
    for (int j = l; j < deg; j += 32) {
        int s = g_csr_src[row + j];
        float e = g_asrc[s] + adv;
        e = (e > 0.0f) ? e : NEG_SLOPE * e;
        float ex = __expf(e);
        sum += ex;
        if (j < WCAP) { sh_src[w][j] = s; sh_ex[w][j] = ex; }
    }
#pragma unroll
    for (int off = 16; off > 0; off >>= 1)
        sum += __shfl_xor_sync(0xFFFFFFFFu, sum, off);
    float inv = 1.0f / (sum + ex_self);
    __syncwarp();

    float4 acc;
    {
        float a = ex_self * inv;
        float4 v = load_xwh(d, l);
        acc.x = a * v.x; acc.y = a * v.y; acc.z = a * v.z; acc.w = a * v.w;
    }
    int m = (deg < WCAP) ? deg : WCAP;
    int j = 0;
    for (; j + 4 <= m; j += 4) {
        int s0 = sh_src[w][j + 0], s1 = sh_src[w][j + 1];
        int s2 = sh_src[w][j + 2], s3 = sh_src[w][j + 3];
        float a0 = sh_ex[w][j + 0] * inv, a1 = sh_ex[w][j + 1] * inv;
        float a2 = sh_ex[w][j + 2] * inv, a3 = sh_ex[w][j + 3] * inv;
        float4 v0 = load_xwh(s0, l);
        float4 v1 = load_xwh(s1, l);
        float4 v2 = load_xwh(s2, l);
        float4 v3 = load_xwh(s3, l);
        acc.x = fmaf(a0, v0.x, acc.x); acc.y = fmaf(a0, v0.y, acc.y);
        acc.z = fmaf(a0, v0.z, acc.z); acc.w = fmaf(a0, v0.w, acc.w);
        acc.x = fmaf(a1, v1.x, acc.x); acc.y = fmaf(a1, v1.y, acc.y);
        acc.z = fmaf(a1, v1.z, acc.z); acc.w = fmaf(a1, v1.w, acc.w);
        acc.x = fmaf(a2, v2.x, acc.x); acc.y = fmaf(a2, v2.y, acc.y);
        acc.z = fmaf(a2, v2.z, acc.z); acc.w = fmaf(a2, v2.w, acc.w);
        acc.x = fmaf(a3, v3.x, acc.x); acc.y = fmaf(a3, v3.y, acc.y);
        acc.z = fmaf(a3, v3.z, acc.z); acc.w = fmaf(a3, v3.w, acc.w);
    }
    for (; j < m; j++) {
        int s = sh_src[w][j];
        float a = sh_ex[w][j] * inv;
        float4 v = load_xwh(s, l);
        acc.x = fmaf(a, v.x, acc.x); acc.y = fmaf(a, v.y, acc.y);
        acc.z = fmaf(a, v.z, acc.z); acc.w = fmaf(a, v.w, acc.w);
    }
    for (int jj = WCAP; jj < deg; jj++) {
        int s = g_csr_src[row + jj];
        float e = g_asrc[s] + adv;
        e = (e > 0.0f) ? e : NEG_SLOPE * e;
        float a = __expf(e) * inv;
        float4 v = load_xwh(s, l);
        acc.x = fmaf(a, v.x, acc.x); acc.y = fmaf(a, v.y, acc.y);
        acc.z = fmaf(a, v.z, acc.z); acc.w = fmaf(a, v.w, acc.w);
    }

    float4 b = *reinterpret_cast<const float4*>(bias + l * 4);
    acc.x += b.x; acc.y += b.y; acc.z += b.z; acc.w += b.w;
    acc.x = (acc.x > 0.0f) ? acc.x : expm1f(acc.x);
    acc.y = (acc.y > 0.0f) ? acc.y : expm1f(acc.y);
    acc.z = (acc.z > 0.0f) ? acc.z : expm1f(acc.z);
    acc.w = (acc.w > 0.0f) ? acc.w : expm1f(acc.w);
    *reinterpret_cast<float4*>(&out[(size_t)d * DOUT + l * 4]) = acc;
}

// ---------------- launch ---------------------------------------------------
extern "C" void kernel_launch(void* const* d_in, const int* in_sizes, int n_in,
                              void* d_out, int out_size) {
    const float* x    = (const float*)d_in[0];
    const int*   ei   = (const int*)d_in[1];    // int32 words (int64 auto-detected)
    const float* W    = (const float*)d_in[2];
    const float* asv  = (const float*)d_in[3];
    const float* adv  = (const float*)d_in[4];
    const float* bias = (const float*)d_in[5];
    float* out = (float*)d_out;

    int n = in_sizes[0] / DIN;      // 50000
    int E = in_sizes[1] / 2;        // 800000
    int nb = (n + 1023) / 1024;     // scan blocks (49)

    int t = 256;
    k_detect<<<1, 32>>>(ei);
    k_gemm<<<(n + 127) / 128, 256>>>(x, W, asv, adv, n);
    k_count<<<(E + 4 * t - 1) / (4 * t), t>>>(ei, E);
    k_scan1<<<nb, 256>>>(n);
    k_scan2<<<1, 32>>>(nb);
    k_scan3<<<(n + t - 1) / t, t>>>(n);
    k_scatter<<<(E + 4 * t - 1) / (4 * t), t>>>(ei, E);
    k_node<<<(n + 7) / 8, t>>>(out, bias, n);
}